// round 2
// baseline (speedup 1.0000x reference)
#include <cuda_runtime.h>
#include <math.h>

#define BB   2048
#define IND  784
#define HH   512
#define OUTD 512
#define NE   8
#define NER  4
#define TT   28
#define G4H  2048

// ---------------- device scratch (no allocation) ----------------
__device__ float g_xproj[(size_t)NER * TT * BB * G4H];  // 1.879 GB
__device__ float g_gates[(size_t)NER * BB * G4H];
__device__ float g_h[2][(size_t)NER * BB * HH];
__device__ float g_c[(size_t)NER * BB * HH];
__device__ float g_w[BB * NE];
__device__ float g_eo[(size_t)NE * BB * OUTD];
__device__ float g_h1[(size_t)NER * BB * HH];

// ---------------- helpers ----------------
__device__ __forceinline__ unsigned tf32r(float x) {
    unsigned u; asm("cvt.rna.tf32.f32 %0, %1;" : "=r"(u) : "f"(x)); return u;
}
__device__ __forceinline__ float fsig(float x) {
    float e; asm("ex2.approx.f32 %0, %1;" : "=f"(e) : "f"(-1.4426950408889634f * x));
    float r; asm("rcp.approx.f32 %0, %1;" : "=f"(r) : "f"(1.0f + e));
    return r;
}
__device__ __forceinline__ float ftanh_(float x) { return fmaf(2.0f, fsig(2.0f * x), -1.0f); }

// ---------------- generic tf32 GEMM: C = A @ B^T (+bias)(+relu) ----------------
// A: [M,K] row-major (lda), B: [N,K] row-major (ldb). Block tile 128x128, BK=32.
// 8 warps: 4 in M x 2 in N, warp tile 32x64 (2 x 8 m16n8k8 frags).
template<int EPI>  // 0 = none, 1 = +bias, 2 = +bias+relu
__global__ __launch_bounds__(256, 2) void gemm_tf32(
    const float* __restrict__ A, int lda, long aStr,
    const float* __restrict__ B, int ldb, long bStr,
    float* __restrict__ C, int ldc, long cStr,
    const float* __restrict__ bias, long biasStr, int K)
{
    __shared__ float As[128 * 32], Bs[128 * 32];
    int z = blockIdx.z;
    A += (long)z * aStr; B += (long)z * bStr; C += (long)z * cStr;
    int m0 = blockIdx.y * 128, n0 = blockIdx.x * 128;
    int tid = threadIdx.x, lane = tid & 31, wid = tid >> 5;
    int wm = wid >> 1, wn = wid & 1;

    float acc[2][8][4];
#pragma unroll
    for (int a = 0; a < 2; a++)
#pragma unroll
        for (int b = 0; b < 8; b++)
#pragma unroll
            for (int c = 0; c < 4; c++) acc[a][b][c] = 0.0f;

    for (int kb = 0; kb < K; kb += 32) {
#pragma unroll
        for (int i = 0; i < 4; i++) {
            int f = tid + i * 256;
            int r = f >> 3, c4 = (f & 7) * 4;
            int k = kb + c4;
            int sc = c4 ^ ((r & 7) << 2);
            float4 v;
            const float* p = A + (long)(m0 + r) * lda + k;
            if (k + 4 <= K) v = *(const float4*)p;
            else { v.x = k < K ? p[0] : 0.f; v.y = k + 1 < K ? p[1] : 0.f;
                   v.z = k + 2 < K ? p[2] : 0.f; v.w = k + 3 < K ? p[3] : 0.f; }
            *(float4*)&As[r * 32 + sc] = v;
            const float* q = B + (long)(n0 + r) * ldb + k;
            if (k + 4 <= K) v = *(const float4*)q;
            else { v.x = k < K ? q[0] : 0.f; v.y = k + 1 < K ? q[1] : 0.f;
                   v.z = k + 2 < K ? q[2] : 0.f; v.w = k + 3 < K ? q[3] : 0.f; }
            *(float4*)&Bs[r * 32 + sc] = v;
        }
        __syncthreads();

#pragma unroll
        for (int ks = 0; ks < 4; ks++) {
            int k0 = ks * 8;
            unsigned af[2][4], bf[8][2];
#pragma unroll
            for (int mt = 0; mt < 2; mt++) {
                int r = wm * 32 + mt * 16 + (lane >> 2);
                int c = k0 + (lane & 3);
                int sw = (r & 7) << 2;
                int r8 = r + 8, sw8 = (r8 & 7) << 2;
                af[mt][0] = tf32r(As[r  * 32 + (c ^ sw)]);
                af[mt][1] = tf32r(As[r8 * 32 + (c ^ sw8)]);
                af[mt][2] = tf32r(As[r  * 32 + ((c + 4) ^ sw)]);
                af[mt][3] = tf32r(As[r8 * 32 + ((c + 4) ^ sw8)]);
            }
#pragma unroll
            for (int nt = 0; nt < 8; nt++) {
                int rn = wn * 64 + nt * 8 + (lane >> 2);
                int ck = k0 + (lane & 3);
                int sw = (rn & 7) << 2;
                bf[nt][0] = tf32r(Bs[rn * 32 + (ck ^ sw)]);
                bf[nt][1] = tf32r(Bs[rn * 32 + ((ck + 4) ^ sw)]);
            }
#pragma unroll
            for (int mt = 0; mt < 2; mt++)
#pragma unroll
                for (int nt = 0; nt < 8; nt++) {
                    asm volatile(
                        "mma.sync.aligned.m16n8k8.row.col.f32.tf32.tf32.f32 "
                        "{%0,%1,%2,%3}, {%4,%5,%6,%7}, {%8,%9}, {%0,%1,%2,%3};\n"
                        : "+f"(acc[mt][nt][0]), "+f"(acc[mt][nt][1]),
                          "+f"(acc[mt][nt][2]), "+f"(acc[mt][nt][3])
                        : "r"(af[mt][0]), "r"(af[mt][1]), "r"(af[mt][2]), "r"(af[mt][3]),
                          "r"(bf[nt][0]), "r"(bf[nt][1]));
                }
        }
        __syncthreads();
    }

    // epilogue
#pragma unroll
    for (int mt = 0; mt < 2; mt++) {
        int r = m0 + wm * 32 + mt * 16 + (lane >> 2);
#pragma unroll
        for (int nt = 0; nt < 8; nt++) {
            int c = n0 + wn * 64 + nt * 8 + (lane & 3) * 2;
            float b0 = 0.f, b1 = 0.f;
            if (EPI >= 1) {
                const float* bp = bias + (long)z * biasStr;
                b0 = bp[c]; b1 = bp[c + 1];
            }
            float v0 = acc[mt][nt][0] + b0, v1 = acc[mt][nt][1] + b1;
            float v2 = acc[mt][nt][2] + b0, v3 = acc[mt][nt][3] + b1;
            if (EPI == 2) {
                v0 = fmaxf(v0, 0.f); v1 = fmaxf(v1, 0.f);
                v2 = fmaxf(v2, 0.f); v3 = fmaxf(v3, 0.f);
            }
            *(float2*)&C[(long)r * ldc + c]       = make_float2(v0, v1);
            *(float2*)&C[(long)(r + 8) * ldc + c] = make_float2(v2, v3);
        }
    }
}

// ---------------- gate: softmax / top-5 / renorm (fp32 exact) ----------------
__global__ void gate_kernel(const float* __restrict__ x, const float* __restrict__ Wg,
                            const float* __restrict__ bg, float* __restrict__ w)
{
    int b = blockIdx.x;
    int lane = threadIdx.x & 31, wid = threadIdx.x >> 5;
    __shared__ float sc[NE];
    const float* xr = x + (long)b * IND;
    const float* wr = Wg + (long)wid * IND;
    float s = 0.f;
    for (int i = lane; i < IND; i += 32) s += xr[i] * wr[i];
#pragma unroll
    for (int o = 16; o; o >>= 1) s += __shfl_xor_sync(0xffffffffu, s, o);
    if (lane == 0) sc[wid] = s + bg[wid];
    __syncthreads();
    if (threadIdx.x == 0) {
        float p[NE], mx = -1e30f;
#pragma unroll
        for (int e = 0; e < NE; e++) { p[e] = sc[e] * (1.0f / 2.718281828459045f); mx = fmaxf(mx, p[e]); }
        float sum = 0.f;
#pragma unroll
        for (int e = 0; e < NE; e++) { p[e] = expf(p[e] - mx); sum += p[e]; }
#pragma unroll
        for (int e = 0; e < NE; e++) p[e] /= sum;
        float ws = 0.f, wv[NE];
#pragma unroll
        for (int e = 0; e < NE; e++) {
            int rank = 0;
#pragma unroll
            for (int j = 0; j < NE; j++)
                if (p[j] > p[e] || (p[j] == p[e] && j < e)) rank++;
            wv[e] = (rank < 5) ? p[e] : 0.f;
            ws += wv[e];
        }
        float inv = 1.0f / (ws + 1e-8f);
#pragma unroll
        for (int e = 0; e < NE; e++) w[b * NE + e] = wv[e] * inv;
    }
}

// ---------------- init: zero h0, c0 ----------------
__global__ void init_state() {
    long i = (long)blockIdx.x * blockDim.x + threadIdx.x;
    g_h[0][i] = 0.f;
    g_c[i] = 0.f;
}

// ---------------- LSTM cell pointwise ----------------
__global__ void lstm_cell(int t, const float* __restrict__ bih,
                          const float* __restrict__ bhh, int outBuf)
{
    long g = (long)blockIdx.x * blockDim.x + threadIdx.x;   // ER*B*H
    int e = (int)(g >> 20);                                  // B*H = 2^20
    int rem = (int)(g & 1048575);
    int b = rem >> 9, u = rem & 511;
    const float* Xp = g_xproj + (((long)(e * TT + t) * BB + b) << 11);
    const float* Gp = g_gates + (((long)e * BB + b) << 11);
    const float* bi = bih + e * G4H;
    const float* bh = bhh + e * G4H;
    float gi = Xp[u]        + Gp[u]        + bi[u]        + bh[u];
    float gf = Xp[u + 512]  + Gp[u + 512]  + bi[u + 512]  + bh[u + 512];
    float gg = Xp[u + 1024] + Gp[u + 1024] + bi[u + 1024] + bh[u + 1024];
    float go = Xp[u + 1536] + Gp[u + 1536] + bi[u + 1536] + bh[u + 1536];
    float iv = fsig(gi), fv = fsig(gf), gv = ftanh_(gg), ov = fsig(go);
    float c = fv * g_c[g] + iv * gv;
    g_c[g] = c;
    g_h[outBuf][g] = ov * ftanh_(c);
}

// ---------------- final combine ----------------
__global__ void combine_kernel(float* __restrict__ out) {
    int idx = blockIdx.x * blockDim.x + threadIdx.x;  // B*OUT
    int b = idx >> 9, o = idx & 511;
    float s = 0.f;
#pragma unroll
    for (int e = 0; e < NE; e++)
        s += g_w[b * NE + e] * g_eo[((long)e * BB + b) * OUTD + o];
    out[idx] = s;
}

// ---------------- launch ----------------
extern "C" void kernel_launch(void* const* d_in, const int* in_sizes, int n_in,
                              void* d_out, int out_size)
{
    const float* x    = (const float*)d_in[0];
    const float* Wg   = (const float*)d_in[1];
    const float* bg   = (const float*)d_in[2];
    const float* Wih  = (const float*)d_in[3];
    const float* Whh  = (const float*)d_in[4];
    const float* bih  = (const float*)d_in[5];
    const float* bhh  = (const float*)d_in[6];
    const float* fcW  = (const float*)d_in[7];
    const float* fcb  = (const float*)d_in[8];
    const float* W1   = (const float*)d_in[9];
    const float* b1   = (const float*)d_in[10];
    const float* W2   = (const float*)d_in[11];
    const float* b2   = (const float*)d_in[12];
    float* out = (float*)d_out;

    float *xp, *gt, *h0p, *h1p, *wp, *eop, *h1buf;
    cudaGetSymbolAddress((void**)&xp,   g_xproj);
    cudaGetSymbolAddress((void**)&gt,   g_gates);
    cudaGetSymbolAddress((void**)&h0p,  g_h);         // g_h[0]
    cudaGetSymbolAddress((void**)&wp,   g_w);
    cudaGetSymbolAddress((void**)&eop,  g_eo);
    cudaGetSymbolAddress((void**)&h1buf, g_h1);
    h1p = h0p + (size_t)NER * BB * HH;                // g_h[1]
    float* hbuf[2] = { h0p, h1p };

    // gate weights
    gate_kernel<<<BB, 256>>>(x, Wg, bg, wp);
    // zero h0 / c0
    init_state<<<(NER * BB * HH) / 256, 256>>>();

    // Xproj: per expert, z = t (28). A = x (aStr=28 per t), B = Wih[e]
    for (int e = 0; e < NER; e++) {
        gemm_tf32<0><<<dim3(16, 16, TT), 256>>>(
            x, IND, 28,
            Wih + (size_t)e * G4H * 28, 28, 0,
            xp + (size_t)e * TT * BB * G4H, G4H, (long)BB * G4H,
            nullptr, 0, 28);
    }

    // recurrent steps
    for (int t = 0; t < TT; t++) {
        int inBuf = t & 1, outBuf = (t + 1) & 1;
        gemm_tf32<0><<<dim3(16, 16, NER), 256>>>(
            hbuf[inBuf], HH, (long)BB * HH,
            Whh, HH, (long)G4H * HH,
            gt, G4H, (long)BB * G4H,
            nullptr, 0, HH);
        lstm_cell<<<(NER * BB * HH) / 256, 256>>>(t, bih, bhh, outBuf);
    }
    float* hLast = hbuf[TT & 1];   // t=27 writes buf 0

    // rec_out = h_last @ fcW^T + fcb  -> g_eo[0..3]
    gemm_tf32<1><<<dim3(4, 16, NER), 256>>>(
        hLast, HH, (long)BB * HH,
        fcW, HH, (long)OUTD * HH,
        eop, OUTD, (long)BB * OUTD,
        fcb, OUTD, HH);

    // h1 = relu(x @ W1^T + b1)
    gemm_tf32<2><<<dim3(4, 16, NER), 256>>>(
        x, IND, 0,
        W1, IND, (long)HH * IND,
        h1buf, HH, (long)BB * HH,
        b1, HH, IND);

    // simp = h1 @ W2^T + b2  -> g_eo[4..7]
    gemm_tf32<1><<<dim3(4, 16, NER), 256>>>(
        h1buf, HH, (long)BB * HH,
        W2, HH, (long)OUTD * HH,
        eop + (size_t)NER * BB * OUTD, OUTD, (long)BB * OUTD,
        b2, OUTD, HH);

    // weighted combine
    combine_kernel<<<(BB * OUTD) / 256, 256>>>(out);
}

// round 3
// speedup vs baseline: 1.3987x; 1.3987x over previous
#include <cuda_runtime.h>
#include <math.h>

#define BB   2048
#define IND  784
#define HH   512
#define OUTD 512
#define NE   8
#define NER  4
#define TT   28
#define G4H  2048
#define KCAT 544

// ---------------- device scratch (no allocation) ----------------
__device__ float g_Wcat[(size_t)NER * G4H * KCAT];   // interleaved [i,f,g,o]/unit, tf32-rounded
__device__ float g_bcat[NER * G4H];                  // bih+bhh, interleaved
__device__ float g_xpad[TT * BB * 32];               // x slices, tf32-rounded, padded
__device__ float g_h[2][(size_t)NER * BB * HH];      // ping-pong hidden (tf32-rounded)
__device__ float g_c[(size_t)NER * BB * HH];         // cell state fp32
__device__ float g_w[BB * NE];
__device__ float g_eo[(size_t)NE * BB * OUTD];
__device__ float g_h1[(size_t)NER * BB * HH];

// ---------------- helpers ----------------
__device__ __forceinline__ unsigned tf32r(float x) {
    unsigned u; asm("cvt.rna.tf32.f32 %0, %1;" : "=r"(u) : "f"(x)); return u;
}
__device__ __forceinline__ float tf32f(float x) { return __uint_as_float(tf32r(x)); }
__device__ __forceinline__ float fsig(float x) {
    float e; asm("ex2.approx.f32 %0, %1;" : "=f"(e) : "f"(-1.4426950408889634f * x));
    float r; asm("rcp.approx.f32 %0, %1;" : "=f"(r) : "f"(1.0f + e));
    return r;
}
__device__ __forceinline__ float ftanh_(float x) { return fmaf(2.0f, fsig(2.0f * x), -1.0f); }
__device__ __forceinline__ void cpa16(float* dst, const float* src) {
    unsigned d = (unsigned)__cvta_generic_to_shared(dst);
    asm volatile("cp.async.cg.shared.global [%0], [%1], 16;\n" :: "r"(d), "l"(src));
}
__device__ __forceinline__ void commitg() { asm volatile("cp.async.commit_group;\n"); }

// ---------------- prep kernels ----------------
__global__ void prep_wcat(const float* __restrict__ Whh, const float* __restrict__ Wih) {
    long i = (long)blockIdx.x * 256 + threadIdx.x;
    if (i >= (long)NER * G4H * KCAT) return;
    int col = (int)(i % KCAT);
    long rr = i / KCAT;
    int row = (int)(rr % G4H);
    int e = (int)(rr / G4H);
    int u = row >> 2, g = row & 3;
    int orow = g * 512 + u;
    float v = 0.0f;
    if (col < 512)      v = Whh[((long)e * G4H + orow) * HH + col];
    else if (col < 540) v = Wih[((long)e * G4H + orow) * 28 + (col - 512)];
    g_Wcat[i] = tf32f(v);
}

__global__ void prep_bcat(const float* __restrict__ bih, const float* __restrict__ bhh) {
    int i = blockIdx.x * 256 + threadIdx.x;   // NER*G4H
    int row = i & (G4H - 1), e = i >> 11;
    int u = row >> 2, g = row & 3;
    int orow = g * 512 + u;
    g_bcat[i] = bih[e * G4H + orow] + bhh[e * G4H + orow];
}

__global__ void prep_xpad(const float* __restrict__ x) {
    int i = blockIdx.x * 256 + threadIdx.x;   // TT*BB*32
    int j = i & 31, b = (i >> 5) & (BB - 1), t = i >> 16;
    g_xpad[i] = (j < 28) ? tf32f(x[(long)b * IND + t * 28 + j]) : 0.0f;
}

__global__ void init_c() {
    long i = (long)blockIdx.x * 256 + threadIdx.x;
    g_c[i] = 0.0f;
}

// ---------------- fused recurrent GEMM + LSTM cell epilogue ----------------
// gates[b, 4u+g] = [h | x_t] @ Wcat^T ; epilogue applies the cell and writes h,c.
__global__ __launch_bounds__(256, 2) void lstm_gemm(
    const float* __restrict__ hIn, float* __restrict__ hOut,
    const float* __restrict__ xpadT, int kStart)
{
    extern __shared__ float sm[];
    float* As = sm;               // [2][128*32]
    float* Bs = sm + 2 * 4096;    // [2][128*32]
    int e = blockIdx.z;
    const float* Ah = hIn + (size_t)e * BB * HH;
    const float* Bw = g_Wcat + (size_t)e * G4H * KCAT;
    int m0 = blockIdx.y * 128, n0 = blockIdx.x * 128;
    int tid = threadIdx.x, lane = tid & 31, wid = tid >> 5;
    int wm = wid >> 1, wn = wid & 1;

    float acc[2][8][4] = {};

    int NSl = (KCAT - kStart) >> 5;

#define LOAD_SLAB(stg, slab) do {                                              \
        int kb = kStart + (slab) * 32;                                         \
        float* Ad = As + (stg) * 4096;                                         \
        float* Bd = Bs + (stg) * 4096;                                         \
        _Pragma("unroll")                                                      \
        for (int i_ = 0; i_ < 4; i_++) {                                       \
            int f_ = tid + i_ * 256;                                           \
            int r_ = f_ >> 3, c4_ = (f_ & 7) * 4;                              \
            int sc_ = c4_ ^ ((r_ & 7) << 2);                                   \
            const float* ga = (kb < 512)                                       \
                ? (Ah + (size_t)(m0 + r_) * HH + kb + c4_)                     \
                : (xpadT + (size_t)(m0 + r_) * 32 + c4_);                      \
            cpa16(Ad + r_ * 32 + sc_, ga);                                     \
            cpa16(Bd + r_ * 32 + sc_, Bw + (size_t)(n0 + r_) * KCAT + kb + c4_);\
        }                                                                      \
        commitg();                                                             \
    } while (0)

    LOAD_SLAB(0, 0);

    for (int s = 0; s < NSl; s++) {
        if (s + 1 < NSl) {
            LOAD_SLAB((s + 1) & 1, s + 1);
            asm volatile("cp.async.wait_group 1;\n");
        } else {
            asm volatile("cp.async.wait_group 0;\n");
        }
        __syncthreads();
        const float* Ac = As + (s & 1) * 4096;
        const float* Bc = Bs + (s & 1) * 4096;
#pragma unroll
        for (int ks = 0; ks < 4; ks++) {
            int k0 = ks * 8;
            unsigned af[2][4], bf[8][2];
#pragma unroll
            for (int mt = 0; mt < 2; mt++) {
                int r = wm * 32 + mt * 16 + (lane >> 2);
                int c = k0 + (lane & 3);
                int sw = (r & 7) << 2;
                int r8 = r + 8, sw8 = (r8 & 7) << 2;
                af[mt][0] = __float_as_uint(Ac[r  * 32 + (c ^ sw)]);
                af[mt][1] = __float_as_uint(Ac[r8 * 32 + (c ^ sw8)]);
                af[mt][2] = __float_as_uint(Ac[r  * 32 + ((c + 4) ^ sw)]);
                af[mt][3] = __float_as_uint(Ac[r8 * 32 + ((c + 4) ^ sw8)]);
            }
#pragma unroll
            for (int nt = 0; nt < 8; nt++) {
                int rn = wn * 64 + nt * 8 + (lane >> 2);
                int ck = k0 + (lane & 3);
                int sw = (rn & 7) << 2;
                bf[nt][0] = __float_as_uint(Bc[rn * 32 + (ck ^ sw)]);
                bf[nt][1] = __float_as_uint(Bc[rn * 32 + ((ck + 4) ^ sw)]);
            }
#pragma unroll
            for (int mt = 0; mt < 2; mt++)
#pragma unroll
                for (int nt = 0; nt < 8; nt++) {
                    asm volatile(
                        "mma.sync.aligned.m16n8k8.row.col.f32.tf32.tf32.f32 "
                        "{%0,%1,%2,%3}, {%4,%5,%6,%7}, {%8,%9}, {%0,%1,%2,%3};\n"
                        : "+f"(acc[mt][nt][0]), "+f"(acc[mt][nt][1]),
                          "+f"(acc[mt][nt][2]), "+f"(acc[mt][nt][3])
                        : "r"(af[mt][0]), "r"(af[mt][1]), "r"(af[mt][2]), "r"(af[mt][3]),
                          "r"(bf[nt][0]), "r"(bf[nt][1]));
                }
        }
        __syncthreads();
    }

    // -------- LSTM cell epilogue --------
    const float* bc = g_bcat + e * G4H;
    float4 bb[8];
#pragma unroll
    for (int nt = 0; nt < 8; nt++) {
        int gc = n0 + wn * 64 + nt * 8 + (lane & 2) * 2;  // even col of this lane's unit
        bb[nt] = *(const float4*)(bc + (gc >> 2) * 4);
    }
    bool evenLane = ((lane & 1) == 0);
    float* cP = g_c + (size_t)e * BB * HH;
    float* hP = hOut + (size_t)e * BB * HH;
#pragma unroll
    for (int mt = 0; mt < 2; mt++) {
#pragma unroll
        for (int nt = 0; nt < 8; nt++) {
            float v0 = acc[mt][nt][0], v1 = acc[mt][nt][1];
            float v2 = acc[mt][nt][2], v3 = acc[mt][nt][3];
            float p0 = __shfl_xor_sync(0xffffffffu, v0, 1);
            float p1 = __shfl_xor_sync(0xffffffffu, v1, 1);
            float p2 = __shfl_xor_sync(0xffffffffu, v2, 1);
            float p3 = __shfl_xor_sync(0xffffffffu, v3, 1);
            int rbase = m0 + wm * 32 + mt * 16 + (lane >> 2);
            int row = evenLane ? rbase : rbase + 8;
            float gi = (evenLane ? v0 : p2) + bb[nt].x;
            float gf = (evenLane ? v1 : p3) + bb[nt].y;
            float gg = (evenLane ? p0 : v2) + bb[nt].z;
            float go = (evenLane ? p1 : v3) + bb[nt].w;
            int gc = n0 + wn * 64 + nt * 8 + (lane & 2) * 2;
            int u = gc >> 2;
            size_t ci = (size_t)row * HH + u;
            float cv = fsig(gf) * cP[ci] + fsig(gi) * ftanh_(gg);
            cP[ci] = cv;
            hP[ci] = tf32f(fsig(go) * ftanh_(cv));
        }
    }
}

// ---------------- generic tf32 GEMM: C = A @ B^T (+bias)(+relu) ----------------
template<int EPI>  // 0 none, 1 +bias, 2 +bias+relu
__global__ __launch_bounds__(256, 2) void gemm_tf32(
    const float* __restrict__ A, int lda, long aStr,
    const float* __restrict__ B, int ldb, long bStr,
    float* __restrict__ C, int ldc, long cStr,
    const float* __restrict__ bias, long biasStr, int K)
{
    __shared__ float As[128 * 32], Bs[128 * 32];
    int z = blockIdx.z;
    A += (long)z * aStr; B += (long)z * bStr; C += (long)z * cStr;
    int m0 = blockIdx.y * 128, n0 = blockIdx.x * 128;
    int tid = threadIdx.x, lane = tid & 31, wid = tid >> 5;
    int wm = wid >> 1, wn = wid & 1;
    float acc[2][8][4] = {};

    for (int kb = 0; kb < K; kb += 32) {
#pragma unroll
        for (int i = 0; i < 4; i++) {
            int f = tid + i * 256;
            int r = f >> 3, c4 = (f & 7) * 4;
            int k = kb + c4;
            int sc = c4 ^ ((r & 7) << 2);
            float4 v;
            const float* p = A + (long)(m0 + r) * lda + k;
            if (k + 4 <= K) v = *(const float4*)p;
            else { v.x = k < K ? p[0] : 0.f; v.y = k + 1 < K ? p[1] : 0.f;
                   v.z = k + 2 < K ? p[2] : 0.f; v.w = k + 3 < K ? p[3] : 0.f; }
            *(float4*)&As[r * 32 + sc] = v;
            const float* q = B + (long)(n0 + r) * ldb + k;
            if (k + 4 <= K) v = *(const float4*)q;
            else { v.x = k < K ? q[0] : 0.f; v.y = k + 1 < K ? q[1] : 0.f;
                   v.z = k + 2 < K ? q[2] : 0.f; v.w = k + 3 < K ? q[3] : 0.f; }
            *(float4*)&Bs[r * 32 + sc] = v;
        }
        __syncthreads();
#pragma unroll
        for (int ks = 0; ks < 4; ks++) {
            int k0 = ks * 8;
            unsigned af[2][4], bf[8][2];
#pragma unroll
            for (int mt = 0; mt < 2; mt++) {
                int r = wm * 32 + mt * 16 + (lane >> 2);
                int c = k0 + (lane & 3);
                int sw = (r & 7) << 2;
                int r8 = r + 8, sw8 = (r8 & 7) << 2;
                af[mt][0] = tf32r(As[r  * 32 + (c ^ sw)]);
                af[mt][1] = tf32r(As[r8 * 32 + (c ^ sw8)]);
                af[mt][2] = tf32r(As[r  * 32 + ((c + 4) ^ sw)]);
                af[mt][3] = tf32r(As[r8 * 32 + ((c + 4) ^ sw8)]);
            }
#pragma unroll
            for (int nt = 0; nt < 8; nt++) {
                int rn = wn * 64 + nt * 8 + (lane >> 2);
                int ck = k0 + (lane & 3);
                int sw = (rn & 7) << 2;
                bf[nt][0] = tf32r(Bs[rn * 32 + (ck ^ sw)]);
                bf[nt][1] = tf32r(Bs[rn * 32 + ((ck + 4) ^ sw)]);
            }
#pragma unroll
            for (int mt = 0; mt < 2; mt++)
#pragma unroll
                for (int nt = 0; nt < 8; nt++) {
                    asm volatile(
                        "mma.sync.aligned.m16n8k8.row.col.f32.tf32.tf32.f32 "
                        "{%0,%1,%2,%3}, {%4,%5,%6,%7}, {%8,%9}, {%0,%1,%2,%3};\n"
                        : "+f"(acc[mt][nt][0]), "+f"(acc[mt][nt][1]),
                          "+f"(acc[mt][nt][2]), "+f"(acc[mt][nt][3])
                        : "r"(af[mt][0]), "r"(af[mt][1]), "r"(af[mt][2]), "r"(af[mt][3]),
                          "r"(bf[nt][0]), "r"(bf[nt][1]));
                }
        }
        __syncthreads();
    }
#pragma unroll
    for (int mt = 0; mt < 2; mt++) {
        int r = m0 + wm * 32 + mt * 16 + (lane >> 2);
#pragma unroll
        for (int nt = 0; nt < 8; nt++) {
            int c = n0 + wn * 64 + nt * 8 + (lane & 3) * 2;
            float b0 = 0.f, b1 = 0.f;
            if (EPI >= 1) {
                const float* bp = bias + (long)z * biasStr;
                b0 = bp[c]; b1 = bp[c + 1];
            }
            float v0 = acc[mt][nt][0] + b0, v1 = acc[mt][nt][1] + b1;
            float v2 = acc[mt][nt][2] + b0, v3 = acc[mt][nt][3] + b1;
            if (EPI == 2) {
                v0 = fmaxf(v0, 0.f); v1 = fmaxf(v1, 0.f);
                v2 = fmaxf(v2, 0.f); v3 = fmaxf(v3, 0.f);
            }
            *(float2*)&C[(long)r * ldc + c]       = make_float2(v0, v1);
            *(float2*)&C[(long)(r + 8) * ldc + c] = make_float2(v2, v3);
        }
    }
}

// ---------------- gate: softmax / top-5 / renorm (fp32 exact) ----------------
__global__ void gate_kernel(const float* __restrict__ x, const float* __restrict__ Wg,
                            const float* __restrict__ bg, float* __restrict__ w)
{
    int b = blockIdx.x;
    int lane = threadIdx.x & 31, wid = threadIdx.x >> 5;
    __shared__ float sc[NE];
    const float* xr = x + (long)b * IND;
    const float* wr = Wg + (long)wid * IND;
    float s = 0.f;
    for (int i = lane; i < IND; i += 32) s += xr[i] * wr[i];
#pragma unroll
    for (int o = 16; o; o >>= 1) s += __shfl_xor_sync(0xffffffffu, s, o);
    if (lane == 0) sc[wid] = s + bg[wid];
    __syncthreads();
    if (threadIdx.x == 0) {
        float p[NE], mx = -1e30f;
#pragma unroll
        for (int e = 0; e < NE; e++) { p[e] = sc[e] * (1.0f / 2.718281828459045f); mx = fmaxf(mx, p[e]); }
        float sum = 0.f;
#pragma unroll
        for (int e = 0; e < NE; e++) { p[e] = expf(p[e] - mx); sum += p[e]; }
#pragma unroll
        for (int e = 0; e < NE; e++) p[e] /= sum;
        float ws = 0.f, wv[NE];
#pragma unroll
        for (int e = 0; e < NE; e++) {
            int rank = 0;
#pragma unroll
            for (int j = 0; j < NE; j++)
                if (p[j] > p[e] || (p[j] == p[e] && j < e)) rank++;
            wv[e] = (rank < 5) ? p[e] : 0.f;
            ws += wv[e];
        }
        float inv = 1.0f / (ws + 1e-8f);
#pragma unroll
        for (int e = 0; e < NE; e++) w[b * NE + e] = wv[e] * inv;
    }
}

// ---------------- final combine ----------------
__global__ void combine_kernel(float* __restrict__ out) {
    int idx = blockIdx.x * blockDim.x + threadIdx.x;  // B*OUT
    int b = idx >> 9, o = idx & 511;
    float s = 0.f;
#pragma unroll
    for (int e = 0; e < NE; e++)
        s += g_w[b * NE + e] * g_eo[((long)e * BB + b) * OUTD + o];
    out[idx] = s;
}

// ---------------- launch ----------------
extern "C" void kernel_launch(void* const* d_in, const int* in_sizes, int n_in,
                              void* d_out, int out_size)
{
    const float* x    = (const float*)d_in[0];
    const float* Wg   = (const float*)d_in[1];
    const float* bg   = (const float*)d_in[2];
    const float* Wih  = (const float*)d_in[3];
    const float* Whh  = (const float*)d_in[4];
    const float* bih  = (const float*)d_in[5];
    const float* bhh  = (const float*)d_in[6];
    const float* fcW  = (const float*)d_in[7];
    const float* fcb  = (const float*)d_in[8];
    const float* W1   = (const float*)d_in[9];
    const float* b1   = (const float*)d_in[10];
    const float* W2   = (const float*)d_in[11];
    const float* b2   = (const float*)d_in[12];
    float* out = (float*)d_out;

    static int smemSet = 0;
    if (!smemSet) {
        cudaFuncSetAttribute(lstm_gemm, cudaFuncAttributeMaxDynamicSharedMemorySize, 65536);
        smemSet = 1;
    }

    float *xp, *h0p, *wp, *eop, *h1buf;
    cudaGetSymbolAddress((void**)&xp,    g_xpad);
    cudaGetSymbolAddress((void**)&h0p,   g_h);
    cudaGetSymbolAddress((void**)&wp,    g_w);
    cudaGetSymbolAddress((void**)&eop,   g_eo);
    cudaGetSymbolAddress((void**)&h1buf, g_h1);
    float* h1p = h0p + (size_t)NER * BB * HH;
    float* hbuf[2] = { h0p, h1p };

    // prep
    prep_wcat<<<(int)(((long)NER * G4H * KCAT + 255) / 256), 256>>>(Whh, Wih);
    prep_bcat<<<(NER * G4H) / 256, 256>>>(bih, bhh);
    prep_xpad<<<(TT * BB * 32) / 256, 256>>>(x);
    init_c<<<(NER * BB * HH) / 256, 256>>>();
    gate_kernel<<<BB, 256>>>(x, Wg, bg, wp);

    // recurrent steps: step t reads g_h[t&1] (unused at t=0), writes g_h[(t+1)&1]
    for (int t = 0; t < TT; t++) {
        lstm_gemm<<<dim3(16, 16, NER), 256, 65536>>>(
            hbuf[t & 1], hbuf[(t + 1) & 1], xp + (size_t)t * BB * 32, t == 0 ? 512 : 0);
    }
    float* hLast = hbuf[TT & 1];   // g_h[0]

    // rec_out = h_last @ fcW^T + fcb  -> g_eo[0..3]
    gemm_tf32<1><<<dim3(4, 16, NER), 256>>>(
        hLast, HH, (long)BB * HH,
        fcW, HH, (long)OUTD * HH,
        eop, OUTD, (long)BB * OUTD,
        fcb, OUTD, HH);

    // h1 = relu(x @ W1^T + b1)
    gemm_tf32<2><<<dim3(4, 16, NER), 256>>>(
        x, IND, 0,
        W1, IND, (long)HH * IND,
        h1buf, HH, (long)BB * HH,
        b1, HH, IND);

    // simp = h1 @ W2^T + b2 -> g_eo[4..7]
    gemm_tf32<1><<<dim3(4, 16, NER), 256>>>(
        h1buf, HH, (long)BB * HH,
        W2, HH, (long)OUTD * HH,
        eop + (size_t)NER * BB * OUTD, OUTD, (long)BB * OUTD,
        b2, OUTD, HH);

    combine_kernel<<<(BB * OUTD) / 256, 256>>>(out);
}

// round 5
// speedup vs baseline: 1.5707x; 1.1230x over previous
#include <cuda_runtime.h>
#include <math.h>

#define BB   2048
#define IND  784
#define HH   512
#define OUTD 512
#define NE   8
#define NER  4
#define TT   28
#define G4H  2048
#define KCAT 544

// ---------------- device scratch (no allocation) ----------------
__device__ float g_Wcat[(size_t)NER * G4H * KCAT];   // interleaved [i,f,g,o]/unit, tf32-rounded
__device__ float g_bcat[NER * G4H];                  // bih+bhh, interleaved
__device__ float g_xpad[TT * BB * 32];               // x slices, tf32-rounded, padded
__device__ float g_h[2][(size_t)NER * BB * HH];      // ping-pong hidden (tf32-rounded)
__device__ float g_c[(size_t)NER * BB * HH];         // cell state fp32
__device__ float g_w[BB * NE];
__device__ float g_eo[(size_t)NE * BB * OUTD];
__device__ float g_h1[(size_t)NER * BB * HH];

// ---------------- helpers ----------------
__device__ __forceinline__ unsigned tf32r(float x) {
    unsigned u; asm("cvt.rna.tf32.f32 %0, %1;" : "=r"(u) : "f"(x)); return u;
}
__device__ __forceinline__ float tf32f(float x) { return __uint_as_float(tf32r(x)); }
__device__ __forceinline__ float fsig(float x) {
    float e; asm("ex2.approx.f32 %0, %1;" : "=f"(e) : "f"(-1.4426950408889634f * x));
    float r; asm("rcp.approx.f32 %0, %1;" : "=f"(r) : "f"(1.0f + e));
    return r;
}
__device__ __forceinline__ float ftanh_(float x) { return fmaf(2.0f, fsig(2.0f * x), -1.0f); }
__device__ __forceinline__ void cpa16(float* dst, const float* src) {
    unsigned d = (unsigned)__cvta_generic_to_shared(dst);
    asm volatile("cp.async.cg.shared.global [%0], [%1], 16;\n" :: "r"(d), "l"(src));
}
__device__ __forceinline__ void commitg() { asm volatile("cp.async.commit_group;\n"); }
__device__ __forceinline__ void ldsm4(unsigned& r0, unsigned& r1, unsigned& r2, unsigned& r3,
                                      unsigned addr) {
    asm volatile("ldmatrix.sync.aligned.m8n8.x4.shared.b16 {%0,%1,%2,%3}, [%4];"
                 : "=r"(r0), "=r"(r1), "=r"(r2), "=r"(r3) : "r"(addr));
}

// ---------------- prep kernels ----------------
__global__ void prep_wcat(const float* __restrict__ Whh, const float* __restrict__ Wih) {
    long i = (long)blockIdx.x * 256 + threadIdx.x;
    if (i >= (long)NER * G4H * KCAT) return;
    int col = (int)(i % KCAT);
    long rr = i / KCAT;
    int row = (int)(rr % G4H);
    int e = (int)(rr / G4H);
    int u = row >> 2, g = row & 3;
    int orow = g * 512 + u;
    float v = 0.0f;
    if (col < 512)      v = Whh[((long)e * G4H + orow) * HH + col];
    else if (col < 540) v = Wih[((long)e * G4H + orow) * 28 + (col - 512)];
    g_Wcat[i] = tf32f(v);
}

__global__ void prep_bcat(const float* __restrict__ bih, const float* __restrict__ bhh) {
    int i = blockIdx.x * 256 + threadIdx.x;   // NER*G4H
    int row = i & (G4H - 1), e = i >> 11;
    int u = row >> 2, g = row & 3;
    int orow = g * 512 + u;
    g_bcat[i] = bih[e * G4H + orow] + bhh[e * G4H + orow];
}

__global__ void prep_xpad(const float* __restrict__ x) {
    int i = blockIdx.x * 256 + threadIdx.x;   // TT*BB*32
    int j = i & 31, b = (i >> 5) & (BB - 1), t = i >> 16;
    g_xpad[i] = (j < 28) ? tf32f(x[(long)b * IND + t * 28 + j]) : 0.0f;
}

__global__ void init_c() {
    long i = (long)blockIdx.x * 256 + threadIdx.x;
    g_c[i] = 0.0f;
}

// ---------------- fused recurrent GEMM + LSTM cell epilogue ----------------
// gates[b, 4u+g] = [h | x_t] @ Wcat^T ; epilogue applies the cell, writes h,c.
// 3-stage cp.async pipeline, ldmatrix fragment loads.
__global__ __launch_bounds__(256, 2) void lstm_gemm(
    const float* __restrict__ hIn, float* __restrict__ hOut,
    const float* __restrict__ xpadT, int kStart)
{
    extern __shared__ float sm[];
    // A stages: sm + st*4096 (floats); B stages: sm + 12288 + st*4096
    unsigned sBase = (unsigned)__cvta_generic_to_shared(sm);
    int e = blockIdx.z;
    const float* Ah = hIn + (size_t)e * BB * HH;
    const float* Bw = g_Wcat + (size_t)e * G4H * KCAT;
    int m0 = blockIdx.y * 128, n0 = blockIdx.x * 128;
    int tid = threadIdx.x, lane = tid & 31, wid = tid >> 5;
    int wm = wid >> 1, wn = wid & 1;

    float acc[2][8][4] = {};
    int NSl = (KCAT - kStart) >> 5;

    // ldmatrix per-thread address components
    int lm_mat = lane >> 3, lm_row = lane & 7;
    unsigned swz = (unsigned)(lm_row << 2);                 // float-unit XOR term
    unsigned aRow = (unsigned)(wm * 32 + (lm_mat & 1) * 8 + lm_row);
    unsigned aCol0 = (unsigned)((lm_mat >> 1) * 4);
    unsigned bRow = (unsigned)(wn * 64 + ((lm_mat >> 1) & 1) * 8 + lm_row);
    unsigned bCol0 = (unsigned)((lm_mat & 1) * 4);

#define LOAD_SLAB(stg, slab) do {                                               \
        int kb = kStart + (slab) * 32;                                          \
        float* Ad = sm + (stg) * 4096;                                          \
        float* Bd = sm + 12288 + (stg) * 4096;                                  \
        _Pragma("unroll")                                                       \
        for (int i_ = 0; i_ < 4; i_++) {                                        \
            int f_ = tid + i_ * 256;                                            \
            int r_ = f_ >> 3, c4_ = (f_ & 7) * 4;                               \
            int sc_ = c4_ ^ ((r_ & 7) << 2);                                    \
            const float* ga = (kb < 512)                                        \
                ? (Ah + (size_t)(m0 + r_) * HH + kb + c4_)                      \
                : (xpadT + (size_t)(m0 + r_) * 32 + c4_);                       \
            cpa16(Ad + r_ * 32 + sc_, ga);                                      \
            cpa16(Bd + r_ * 32 + sc_, Bw + (size_t)(n0 + r_) * KCAT + kb + c4_);\
        }                                                                       \
        commitg();                                                              \
    } while (0)

    LOAD_SLAB(0, 0);
    if (NSl > 1) LOAD_SLAB(1, 1);

    int stage = 0;
    for (int s = 0; s < NSl; s++) {
        if (s < NSl - 1) asm volatile("cp.async.wait_group 1;\n");
        else             asm volatile("cp.async.wait_group 0;\n");
        __syncthreads();
        if (s + 2 < NSl) {
            int nst = stage + 2; if (nst >= 3) nst -= 3;
            LOAD_SLAB(nst, s + 2);
        }
        unsigned aStage = sBase + (unsigned)(stage * 4096) * 4u;
        unsigned bStage = sBase + (unsigned)(12288 + stage * 4096) * 4u;
#pragma unroll
        for (int ks = 0; ks < 4; ks++) {
            unsigned kbase = (unsigned)(ks * 8);
            unsigned af[2][4], bf[8][2];
#pragma unroll
            for (int mt = 0; mt < 2; mt++) {
                unsigned r = aRow + (unsigned)(mt * 16);
                unsigned c = (kbase + aCol0) ^ swz;
                ldsm4(af[mt][0], af[mt][1], af[mt][2], af[mt][3],
                      aStage + (r * 32 + c) * 4u);
            }
#pragma unroll
            for (int pp = 0; pp < 4; pp++) {
                unsigned r = bRow + (unsigned)(pp * 16);
                unsigned c = (kbase + bCol0) ^ swz;
                ldsm4(bf[2 * pp][0], bf[2 * pp][1], bf[2 * pp + 1][0], bf[2 * pp + 1][1],
                      bStage + (r * 32 + c) * 4u);
            }
#pragma unroll
            for (int mt = 0; mt < 2; mt++)
#pragma unroll
                for (int nt = 0; nt < 8; nt++) {
                    asm volatile(
                        "mma.sync.aligned.m16n8k8.row.col.f32.tf32.tf32.f32 "
                        "{%0,%1,%2,%3}, {%4,%5,%6,%7}, {%8,%9}, {%0,%1,%2,%3};\n"
                        : "+f"(acc[mt][nt][0]), "+f"(acc[mt][nt][1]),
                          "+f"(acc[mt][nt][2]), "+f"(acc[mt][nt][3])
                        : "r"(af[mt][0]), "r"(af[mt][1]), "r"(af[mt][2]), "r"(af[mt][3]),
                          "r"(bf[nt][0]), "r"(bf[nt][1]));
                }
        }
        stage++; if (stage >= 3) stage = 0;
    }

    // -------- LSTM cell epilogue --------
    const float* bc = g_bcat + e * G4H;
    float4 bb[8];
#pragma unroll
    for (int nt = 0; nt < 8; nt++) {
        int gc = n0 + wn * 64 + nt * 8 + (lane & 2) * 2;  // even col of this lane's unit
        bb[nt] = *(const float4*)(bc + (gc >> 2) * 4);
    }
    bool evenLane = ((lane & 1) == 0);
    float* cP = g_c + (size_t)e * BB * HH;
    float* hP = hOut + (size_t)e * BB * HH;
#pragma unroll
    for (int mt = 0; mt < 2; mt++) {
#pragma unroll
        for (int nt = 0; nt < 8; nt++) {
            float v0 = acc[mt][nt][0], v1 = acc[mt][nt][1];
            float v2 = acc[mt][nt][2], v3 = acc[mt][nt][3];
            float p0 = __shfl_xor_sync(0xffffffffu, v0, 1);
            float p1 = __shfl_xor_sync(0xffffffffu, v1, 1);
            float p2 = __shfl_xor_sync(0xffffffffu, v2, 1);
            float p3 = __shfl_xor_sync(0xffffffffu, v3, 1);
            int rbase = m0 + wm * 32 + mt * 16 + (lane >> 2);
            int row = evenLane ? rbase : rbase + 8;
            float gi = (evenLane ? v0 : p2) + bb[nt].x;
            float gf = (evenLane ? v1 : p3) + bb[nt].y;
            float gg = (evenLane ? p0 : v2) + bb[nt].z;
            float go = (evenLane ? p1 : v3) + bb[nt].w;
            int gc = n0 + wn * 64 + nt * 8 + (lane & 2) * 2;
            int u = gc >> 2;
            size_t ci = (size_t)row * HH + u;
            float cv = fsig(gf) * cP[ci] + fsig(gi) * ftanh_(gg);
            cP[ci] = cv;
            hP[ci] = tf32f(fsig(go) * ftanh_(cv));
        }
    }
}

// ---------------- generic tf32 GEMM: C = A @ B^T (+bias)(+relu) ----------------
template<int EPI>  // 0 none, 1 +bias, 2 +bias+relu
__global__ __launch_bounds__(256, 2) void gemm_tf32(
    const float* __restrict__ A, int lda, long aStr,
    const float* __restrict__ B, int ldb, long bStr,
    float* __restrict__ C, int ldc, long cStr,
    const float* __restrict__ bias, long biasStr, int K)
{
    __shared__ float As[128 * 32], Bs[128 * 32];
    int z = blockIdx.z;
    A += (long)z * aStr; B += (long)z * bStr; C += (long)z * cStr;
    int m0 = blockIdx.y * 128, n0 = blockIdx.x * 128;
    int tid = threadIdx.x, lane = tid & 31, wid = tid >> 5;
    int wm = wid >> 1, wn = wid & 1;
    float acc[2][8][4] = {};

    for (int kb = 0; kb < K; kb += 32) {
#pragma unroll
        for (int i = 0; i < 4; i++) {
            int f = tid + i * 256;
            int r = f >> 3, c4 = (f & 7) * 4;
            int k = kb + c4;
            int sc = c4 ^ ((r & 7) << 2);
            float4 v;
            const float* p = A + (long)(m0 + r) * lda + k;
            if (k + 4 <= K) v = *(const float4*)p;
            else { v.x = k < K ? p[0] : 0.f; v.y = k + 1 < K ? p[1] : 0.f;
                   v.z = k + 2 < K ? p[2] : 0.f; v.w = k + 3 < K ? p[3] : 0.f; }
            *(float4*)&As[r * 32 + sc] = v;
            const float* q = B + (long)(n0 + r) * ldb + k;
            if (k + 4 <= K) v = *(const float4*)q;
            else { v.x = k < K ? q[0] : 0.f; v.y = k + 1 < K ? q[1] : 0.f;
                   v.z = k + 2 < K ? q[2] : 0.f; v.w = k + 3 < K ? q[3] : 0.f; }
            *(float4*)&Bs[r * 32 + sc] = v;
        }
        __syncthreads();
#pragma unroll
        for (int ks = 0; ks < 4; ks++) {
            int k0 = ks * 8;
            unsigned af[2][4], bf[8][2];
#pragma unroll
            for (int mt = 0; mt < 2; mt++) {
                int r = wm * 32 + mt * 16 + (lane >> 2);
                int c = k0 + (lane & 3);
                int sw = (r & 7) << 2;
                int r8 = r + 8, sw8 = (r8 & 7) << 2;
                af[mt][0] = tf32r(As[r  * 32 + (c ^ sw)]);
                af[mt][1] = tf32r(As[r8 * 32 + (c ^ sw8)]);
                af[mt][2] = tf32r(As[r  * 32 + ((c + 4) ^ sw)]);
                af[mt][3] = tf32r(As[r8 * 32 + ((c + 4) ^ sw8)]);
            }
#pragma unroll
            for (int nt = 0; nt < 8; nt++) {
                int rn = wn * 64 + nt * 8 + (lane >> 2);
                int ck = k0 + (lane & 3);
                int sw = (rn & 7) << 2;
                bf[nt][0] = tf32r(Bs[rn * 32 + (ck ^ sw)]);
                bf[nt][1] = tf32r(Bs[rn * 32 + ((ck + 4) ^ sw)]);
            }
#pragma unroll
            for (int mt = 0; mt < 2; mt++)
#pragma unroll
                for (int nt = 0; nt < 8; nt++) {
                    asm volatile(
                        "mma.sync.aligned.m16n8k8.row.col.f32.tf32.tf32.f32 "
                        "{%0,%1,%2,%3}, {%4,%5,%6,%7}, {%8,%9}, {%0,%1,%2,%3};\n"
                        : "+f"(acc[mt][nt][0]), "+f"(acc[mt][nt][1]),
                          "+f"(acc[mt][nt][2]), "+f"(acc[mt][nt][3])
                        : "r"(af[mt][0]), "r"(af[mt][1]), "r"(af[mt][2]), "r"(af[mt][3]),
                          "r"(bf[nt][0]), "r"(bf[nt][1]));
                }
        }
        __syncthreads();
    }
#pragma unroll
    for (int mt = 0; mt < 2; mt++) {
        int r = m0 + wm * 32 + mt * 16 + (lane >> 2);
#pragma unroll
        for (int nt = 0; nt < 8; nt++) {
            int c = n0 + wn * 64 + nt * 8 + (lane & 3) * 2;
            float b0 = 0.f, b1 = 0.f;
            if (EPI >= 1) {
                const float* bp = bias + (long)z * biasStr;
                b0 = bp[c]; b1 = bp[c + 1];
            }
            float v0 = acc[mt][nt][0] + b0, v1 = acc[mt][nt][1] + b1;
            float v2 = acc[mt][nt][2] + b0, v3 = acc[mt][nt][3] + b1;
            if (EPI == 2) {
                v0 = fmaxf(v0, 0.f); v1 = fmaxf(v1, 0.f);
                v2 = fmaxf(v2, 0.f); v3 = fmaxf(v3, 0.f);
            }
            *(float2*)&C[(long)r * ldc + c]       = make_float2(v0, v1);
            *(float2*)&C[(long)(r + 8) * ldc + c] = make_float2(v2, v3);
        }
    }
}

// ---------------- gate: softmax / top-5 / renorm (fp32 exact) ----------------
__global__ void gate_kernel(const float* __restrict__ x, const float* __restrict__ Wg,
                            const float* __restrict__ bg, float* __restrict__ w)
{
    int b = blockIdx.x;
    int lane = threadIdx.x & 31, wid = threadIdx.x >> 5;
    __shared__ float sc[NE];
    const float* xr = x + (long)b * IND;
    const float* wr = Wg + (long)wid * IND;
    float s = 0.f;
    for (int i = lane; i < IND; i += 32) s += xr[i] * wr[i];
#pragma unroll
    for (int o = 16; o; o >>= 1) s += __shfl_xor_sync(0xffffffffu, s, o);
    if (lane == 0) sc[wid] = s + bg[wid];
    __syncthreads();
    if (threadIdx.x == 0) {
        float p[NE], mx = -1e30f;
#pragma unroll
        for (int e = 0; e < NE; e++) { p[e] = sc[e] * (1.0f / 2.718281828459045f); mx = fmaxf(mx, p[e]); }
        float sum = 0.f;
#pragma unroll
        for (int e = 0; e < NE; e++) { p[e] = expf(p[e] - mx); sum += p[e]; }
#pragma unroll
        for (int e = 0; e < NE; e++) p[e] /= sum;
        float ws = 0.f, wv[NE];
#pragma unroll
        for (int e = 0; e < NE; e++) {
            int rank = 0;
#pragma unroll
            for (int j = 0; j < NE; j++)
                if (p[j] > p[e] || (p[j] == p[e] && j < e)) rank++;
            wv[e] = (rank < 5) ? p[e] : 0.f;
            ws += wv[e];
        }
        float inv = 1.0f / (ws + 1e-8f);
#pragma unroll
        for (int e = 0; e < NE; e++) w[b * NE + e] = wv[e] * inv;
    }
}

// ---------------- final combine ----------------
__global__ void combine_kernel(float* __restrict__ out) {
    int idx = blockIdx.x * blockDim.x + threadIdx.x;  // B*OUT
    int b = idx >> 9, o = idx & 511;
    float s = 0.f;
#pragma unroll
    for (int e = 0; e < NE; e++)
        s += g_w[b * NE + e] * g_eo[((long)e * BB + b) * OUTD + o];
    out[idx] = s;
}

// ---------------- launch ----------------
extern "C" void kernel_launch(void* const* d_in, const int* in_sizes, int n_in,
                              void* d_out, int out_size)
{
    const float* x    = (const float*)d_in[0];
    const float* Wg   = (const float*)d_in[1];
    const float* bg   = (const float*)d_in[2];
    const float* Wih  = (const float*)d_in[3];
    const float* Whh  = (const float*)d_in[4];
    const float* bih  = (const float*)d_in[5];
    const float* bhh  = (const float*)d_in[6];
    const float* fcW  = (const float*)d_in[7];
    const float* fcb  = (const float*)d_in[8];
    const float* W1   = (const float*)d_in[9];
    const float* b1   = (const float*)d_in[10];
    const float* W2   = (const float*)d_in[11];
    const float* b2   = (const float*)d_in[12];
    float* out = (float*)d_out;

    cudaFuncSetAttribute(lstm_gemm, cudaFuncAttributeMaxDynamicSharedMemorySize, 98304);

    float *xp, *h0p, *wp, *eop, *h1buf;
    cudaGetSymbolAddress((void**)&xp,    g_xpad);
    cudaGetSymbolAddress((void**)&h0p,   g_h);
    cudaGetSymbolAddress((void**)&wp,    g_w);
    cudaGetSymbolAddress((void**)&eop,   g_eo);
    cudaGetSymbolAddress((void**)&h1buf, g_h1);
    float* h1p = h0p + (size_t)NER * BB * HH;
    float* hbuf[2] = { h0p, h1p };

    // prep
    prep_wcat<<<(int)(((long)NER * G4H * KCAT + 255) / 256), 256>>>(Whh, Wih);
    prep_bcat<<<(NER * G4H) / 256, 256>>>(bih, bhh);
    prep_xpad<<<(TT * BB * 32) / 256, 256>>>(x);
    init_c<<<(NER * BB * HH) / 256, 256>>>();
    gate_kernel<<<BB, 256>>>(x, Wg, bg, wp);

    // recurrent steps: step t reads g_h[t&1] (unused at t=0), writes g_h[(t+1)&1]
    for (int t = 0; t < TT; t++) {
        lstm_gemm<<<dim3(16, 16, NER), 256, 98304>>>(
            hbuf[t & 1], hbuf[(t + 1) & 1], xp + (size_t)t * BB * 32, t == 0 ? 512 : 0);
    }
    float* hLast = hbuf[TT & 1];   // g_h[0]

    // rec_out = h_last @ fcW^T + fcb  -> g_eo[0..3]
    gemm_tf32<1><<<dim3(4, 16, NER), 256>>>(
        hLast, HH, (long)BB * HH,
        fcW, HH, (long)OUTD * HH,
        eop, OUTD, (long)BB * OUTD,
        fcb, OUTD, HH);

    // h1 = relu(x @ W1^T + b1)
    gemm_tf32<2><<<dim3(4, 16, NER), 256>>>(
        x, IND, 0,
        W1, IND, (long)HH * IND,
        h1buf, HH, (long)BB * HH,
        b1, HH, IND);

    // simp = h1 @ W2^T + b2 -> g_eo[4..7]
    gemm_tf32<1><<<dim3(4, 16, NER), 256>>>(
        h1buf, HH, (long)BB * HH,
        W2, HH, (long)OUTD * HH,
        eop + (size_t)NER * BB * OUTD, OUTD, (long)BB * OUTD,
        b2, OUTD, HH);

    combine_kernel<<<(BB * OUTD) / 256, 256>>>(out);
}

// round 7
// speedup vs baseline: 2.1759x; 1.3853x over previous
#include <cuda_runtime.h>
#include <math.h>

#define BB   2048
#define IND  784
#define HH   512
#define OUTD 512
#define NE   8
#define NER  4
#define TT   28
#define G4H  2048
#define KCAT 544

// ---------------- device scratch (no allocation) ----------------
__device__ float g_Wcat[(size_t)NER * G4H * KCAT];   // interleaved [i,f,g,o]/unit, tf32-rounded
__device__ float g_bcat[NER * G4H];                  // bih+bhh, interleaved
__device__ float g_xpad[TT * BB * 32];               // x slices, tf32-rounded, padded
__device__ float g_h[2][(size_t)NER * BB * HH];      // ping-pong hidden, COMPACT rows
__device__ float g_c[(size_t)NER * BB * HH];         // cell state fp32, COMPACT rows
__device__ float g_w[BB * NE];
__device__ float g_eo[(size_t)NE * BB * OUTD];       // zero-init; only selected rows written (e<4)
__device__ float g_h1[(size_t)NER * BB * HH];
__device__ int   g_sel[NE * BB];                     // selection mask, expert-major
__device__ int   g_idx[NER * BB];                    // compact->batch index per expert
__device__ int   g_cnt[NER];                         // selected count per expert

// ---------------- helpers ----------------
__device__ __forceinline__ unsigned tf32r(float x) {
    unsigned u; asm("cvt.rna.tf32.f32 %0, %1;" : "=r"(u) : "f"(x)); return u;
}
__device__ __forceinline__ float tf32f(float x) { return __uint_as_float(tf32r(x)); }
__device__ __forceinline__ float fsig(float x) {
    float e; asm("ex2.approx.f32 %0, %1;" : "=f"(e) : "f"(-1.4426950408889634f * x));
    float r; asm("rcp.approx.f32 %0, %1;" : "=f"(r) : "f"(1.0f + e));
    return r;
}
__device__ __forceinline__ float ftanh_(float x) { return fmaf(2.0f, fsig(2.0f * x), -1.0f); }
__device__ __forceinline__ void cpa16(float* dst, const float* src) {
    unsigned d = (unsigned)__cvta_generic_to_shared(dst);
    asm volatile("cp.async.cg.shared.global [%0], [%1], 16;\n" :: "r"(d), "l"(src));
}
__device__ __forceinline__ void commitg() { asm volatile("cp.async.commit_group;\n"); }
__device__ __forceinline__ void ldsm4(unsigned& r0, unsigned& r1, unsigned& r2, unsigned& r3,
                                      unsigned addr) {
    asm volatile("ldmatrix.sync.aligned.m8n8.x4.shared.b16 {%0,%1,%2,%3}, [%4];"
                 : "=r"(r0), "=r"(r1), "=r"(r2), "=r"(r3) : "r"(addr));
}

// ---------------- prep kernels ----------------
__global__ void prep_wcat(const float* __restrict__ Whh, const float* __restrict__ Wih) {
    long i = (long)blockIdx.x * 256 + threadIdx.x;
    if (i >= (long)NER * G4H * KCAT) return;
    int col = (int)(i % KCAT);
    long rr = i / KCAT;
    int row = (int)(rr % G4H);
    int e = (int)(rr / G4H);
    int u = row >> 2, g = row & 3;
    int orow = g * 512 + u;
    float v = 0.0f;
    if (col < 512)      v = Whh[((long)e * G4H + orow) * HH + col];
    else if (col < 540) v = Wih[((long)e * G4H + orow) * 28 + (col - 512)];
    g_Wcat[i] = tf32f(v);
}

__global__ void prep_bcat(const float* __restrict__ bih, const float* __restrict__ bhh) {
    int i = blockIdx.x * 256 + threadIdx.x;   // NER*G4H
    int row = i & (G4H - 1), e = i >> 11;
    int u = row >> 2, g = row & 3;
    int orow = g * 512 + u;
    g_bcat[i] = bih[e * G4H + orow] + bhh[e * G4H + orow];
}

// xpad prep + c zero (folded so the first lstm_gemm is the 6th launch for ncu -s 5)
__global__ void prep_xpad(const float* __restrict__ x) {
    int i = blockIdx.x * 256 + threadIdx.x;   // TT*BB*32 = 1.83M threads
    int j = i & 31, b = (i >> 5) & (BB - 1), t = i >> 16;
    g_xpad[i] = (j < 28) ? tf32f(x[(long)b * IND + t * 28 + j]) : 0.0f;
    for (long k = i; k < (long)NER * BB * HH; k += (long)gridDim.x * 256)
        g_c[k] = 0.0f;
}

// ---------------- gate: softmax / top-5 / renorm (fp32 exact) + selection mask ----------------
__global__ void gate_kernel(const float* __restrict__ x, const float* __restrict__ Wg,
                            const float* __restrict__ bg, float* __restrict__ w)
{
    int b = blockIdx.x;
    int lane = threadIdx.x & 31, wid = threadIdx.x >> 5;
    __shared__ float sc[NE];
    const float* xr = x + (long)b * IND;
    const float* wr = Wg + (long)wid * IND;
    float s = 0.f;
    for (int i = lane; i < IND; i += 32) s += xr[i] * wr[i];
#pragma unroll
    for (int o = 16; o; o >>= 1) s += __shfl_xor_sync(0xffffffffu, s, o);
    if (lane == 0) sc[wid] = s + bg[wid];
    __syncthreads();
    if (threadIdx.x == 0) {
        float p[NE], mx = -1e30f;
#pragma unroll
        for (int e = 0; e < NE; e++) { p[e] = sc[e] * (1.0f / 2.718281828459045f); mx = fmaxf(mx, p[e]); }
        float sum = 0.f;
#pragma unroll
        for (int e = 0; e < NE; e++) { p[e] = expf(p[e] - mx); sum += p[e]; }
#pragma unroll
        for (int e = 0; e < NE; e++) p[e] /= sum;
        float ws = 0.f, wv[NE];
        int selv[NE];
#pragma unroll
        for (int e = 0; e < NE; e++) {
            int rank = 0;
#pragma unroll
            for (int j = 0; j < NE; j++)
                if (p[j] > p[e] || (p[j] == p[e] && j < e)) rank++;
            selv[e] = (rank < 5) ? 1 : 0;
            wv[e] = selv[e] ? p[e] : 0.f;
            ws += wv[e];
        }
        float inv = 1.0f / (ws + 1e-8f);
#pragma unroll
        for (int e = 0; e < NE; e++) {
            w[b * NE + e] = wv[e] * inv;
            g_sel[e * BB + b] = selv[e];
        }
    }
}

// ---------------- per-expert compaction (block scan, 1024 thr, 2048 elems) ----------------
__global__ void compact_kernel() {
    int e = blockIdx.x;             // NER
    int tid = threadIdx.x;          // 1024
    __shared__ int scn[BB];
    scn[tid]        = g_sel[e * BB + tid];
    scn[tid + 1024] = g_sel[e * BB + tid + 1024];
    __syncthreads();
    for (int off = 1; off < BB; off <<= 1) {
        int v0 = (tid >= off) ? scn[tid - off] : 0;
        int v1 = (tid + 1024 >= off) ? scn[tid + 1024 - off] : 0;
        __syncthreads();
        scn[tid] += v0; scn[tid + 1024] += v1;
        __syncthreads();
    }
    int cnt = scn[BB - 1];
    if (g_sel[e * BB + tid])        g_idx[e * BB + scn[tid] - 1] = tid;
    if (g_sel[e * BB + tid + 1024]) g_idx[e * BB + scn[tid + 1024] - 1] = tid + 1024;
    // pad region -> idx 0 (deterministic, in-range reads)
    if (tid + cnt < BB)        g_idx[e * BB + cnt + tid] = 0;
    if (tid + 1024 + cnt < BB) g_idx[e * BB + cnt + tid + 1024] = 0;
    if (tid == 0) g_cnt[e] = cnt;
}

// ---------------- fused recurrent GEMM + LSTM cell (COMPACT rows) ----------------
// 3-stage cp.async pipeline, ldmatrix fragment loads. smem: [0:512) idx, then stages.
__global__ __launch_bounds__(256, 2) void lstm_gemm(
    const float* __restrict__ hIn, float* __restrict__ hOut,
    const float* __restrict__ xpadT, int kStart)
{
    extern __shared__ float sm[];
    int* sIdx = (int*)sm;                       // 128 ints
    float* stg = sm + 128;                      // stages base
    unsigned sBase = (unsigned)__cvta_generic_to_shared(stg);
    int e = blockIdx.z;
    int cnt = g_cnt[e];
    int tiles = (cnt + 127) >> 7;
    if ((int)blockIdx.y >= tiles) return;       // uniform per CTA
    const float* Ah = hIn + (size_t)e * BB * HH;
    const float* Bw = g_Wcat + (size_t)e * G4H * KCAT;
    int m0 = blockIdx.y * 128, n0 = blockIdx.x * 128;
    int tid = threadIdx.x, lane = tid & 31, wid = tid >> 5;
    int wm = wid >> 1, wn = wid & 1;

    if (tid < 128) sIdx[tid] = g_idx[e * BB + m0 + tid];
    __syncthreads();

    float acc[2][8][4] = {};
    int NSl = (KCAT - kStart) >> 5;

    // ldmatrix per-thread address components
    int lm_mat = lane >> 3, lm_row = lane & 7;
    unsigned swz = (unsigned)(lm_row << 2);
    unsigned aRow = (unsigned)(wm * 32 + (lm_mat & 1) * 8 + lm_row);
    unsigned aCol0 = (unsigned)((lm_mat >> 1) * 4);
    unsigned bRow = (unsigned)(wn * 64 + ((lm_mat >> 1) & 1) * 8 + lm_row);
    unsigned bCol0 = (unsigned)((lm_mat & 1) * 4);

#define LOAD_SLAB(stg_, slab) do {                                              \
        int kb = kStart + (slab) * 32;                                          \
        float* Ad = stg + (stg_) * 4096;                                        \
        float* Bd = stg + 12288 + (stg_) * 4096;                                \
        _Pragma("unroll")                                                       \
        for (int i_ = 0; i_ < 4; i_++) {                                        \
            int f_ = tid + i_ * 256;                                            \
            int r_ = f_ >> 3, c4_ = (f_ & 7) * 4;                               \
            int sc_ = c4_ ^ ((r_ & 7) << 2);                                    \
            const float* ga = (kb < 512)                                        \
                ? (Ah + (size_t)(m0 + r_) * HH + kb + c4_)                      \
                : (xpadT + (size_t)sIdx[r_] * 32 + c4_);                        \
            cpa16(Ad + r_ * 32 + sc_, ga);                                      \
            cpa16(Bd + r_ * 32 + sc_, Bw + (size_t)(n0 + r_) * KCAT + kb + c4_);\
        }                                                                       \
        commitg();                                                              \
    } while (0)

    LOAD_SLAB(0, 0);
    if (NSl > 1) LOAD_SLAB(1, 1);

    int stage = 0;
    for (int s = 0; s < NSl; s++) {
        if (s < NSl - 1) asm volatile("cp.async.wait_group 1;\n");
        else             asm volatile("cp.async.wait_group 0;\n");
        __syncthreads();
        if (s + 2 < NSl) {
            int nst = stage + 2; if (nst >= 3) nst -= 3;
            LOAD_SLAB(nst, s + 2);
        }
        unsigned aStage = sBase + (unsigned)(stage * 4096) * 4u;
        unsigned bStage = sBase + (unsigned)(12288 + stage * 4096) * 4u;
#pragma unroll
        for (int ks = 0; ks < 4; ks++) {
            unsigned kbase = (unsigned)(ks * 8);
            unsigned af[2][4], bf[8][2];
#pragma unroll
            for (int mt = 0; mt < 2; mt++) {
                unsigned r = aRow + (unsigned)(mt * 16);
                unsigned c = (kbase + aCol0) ^ swz;
                ldsm4(af[mt][0], af[mt][1], af[mt][2], af[mt][3],
                      aStage + (r * 32 + c) * 4u);
            }
#pragma unroll
            for (int pp = 0; pp < 4; pp++) {
                unsigned r = bRow + (unsigned)(pp * 16);
                unsigned c = (kbase + bCol0) ^ swz;
                ldsm4(bf[2 * pp][0], bf[2 * pp][1], bf[2 * pp + 1][0], bf[2 * pp + 1][1],
                      bStage + (r * 32 + c) * 4u);
            }
#pragma unroll
            for (int mt = 0; mt < 2; mt++)
#pragma unroll
                for (int nt = 0; nt < 8; nt++) {
                    asm volatile(
                        "mma.sync.aligned.m16n8k8.row.col.f32.tf32.tf32.f32 "
                        "{%0,%1,%2,%3}, {%4,%5,%6,%7}, {%8,%9}, {%0,%1,%2,%3};\n"
                        : "+f"(acc[mt][nt][0]), "+f"(acc[mt][nt][1]),
                          "+f"(acc[mt][nt][2]), "+f"(acc[mt][nt][3])
                        : "r"(af[mt][0]), "r"(af[mt][1]), "r"(af[mt][2]), "r"(af[mt][3]),
                          "r"(bf[nt][0]), "r"(bf[nt][1]));
                }
        }
        stage++; if (stage >= 3) stage = 0;
    }

    // -------- LSTM cell epilogue (compact rows) --------
    const float* bc = g_bcat + e * G4H;
    float4 bb[8];
#pragma unroll
    for (int nt = 0; nt < 8; nt++) {
        int gc = n0 + wn * 64 + nt * 8 + (lane & 2) * 2;
        bb[nt] = *(const float4*)(bc + (gc >> 2) * 4);
    }
    bool evenLane = ((lane & 1) == 0);
    float* cP = g_c + (size_t)e * BB * HH;
    float* hP = hOut + (size_t)e * BB * HH;
#pragma unroll
    for (int mt = 0; mt < 2; mt++) {
#pragma unroll
        for (int nt = 0; nt < 8; nt++) {
            float v0 = acc[mt][nt][0], v1 = acc[mt][nt][1];
            float v2 = acc[mt][nt][2], v3 = acc[mt][nt][3];
            float p0 = __shfl_xor_sync(0xffffffffu, v0, 1);
            float p1 = __shfl_xor_sync(0xffffffffu, v1, 1);
            float p2 = __shfl_xor_sync(0xffffffffu, v2, 1);
            float p3 = __shfl_xor_sync(0xffffffffu, v3, 1);
            int rbase = m0 + wm * 32 + mt * 16 + (lane >> 2);
            int row = evenLane ? rbase : rbase + 8;
            float gi = (evenLane ? v0 : p2) + bb[nt].x;
            float gf = (evenLane ? v1 : p3) + bb[nt].y;
            float gg = (evenLane ? p0 : v2) + bb[nt].z;
            float go = (evenLane ? p1 : v3) + bb[nt].w;
            int gc = n0 + wn * 64 + nt * 8 + (lane & 2) * 2;
            int u = gc >> 2;
            size_t ci = (size_t)row * HH + u;
            float cv = fsig(gf) * cP[ci] + fsig(gi) * ftanh_(gg);
            cP[ci] = cv;
            hP[ci] = tf32f(fsig(go) * ftanh_(cv));
        }
    }
}

// ---------------- generic tf32 GEMM: C = A @ B^T (+bias)(+relu) ----------------
template<int EPI>  // 1 +bias, 2 +bias+relu
__global__ __launch_bounds__(256, 2) void gemm_tf32(
    const float* __restrict__ A, int lda, long aStr,
    const float* __restrict__ B, int ldb, long bStr,
    float* __restrict__ C, int ldc, long cStr,
    const float* __restrict__ bias, long biasStr, int K)
{
    __shared__ float As[128 * 32], Bs[128 * 32];
    int z = blockIdx.z;
    A += (long)z * aStr; B += (long)z * bStr; C += (long)z * cStr;
    int m0 = blockIdx.y * 128, n0 = blockIdx.x * 128;
    int tid = threadIdx.x, lane = tid & 31, wid = tid >> 5;
    int wm = wid >> 1, wn = wid & 1;
    float acc[2][8][4] = {};

    for (int kb = 0; kb < K; kb += 32) {
#pragma unroll
        for (int i = 0; i < 4; i++) {
            int f = tid + i * 256;
            int r = f >> 3, c4 = (f & 7) * 4;
            int k = kb + c4;
            int sc = c4 ^ ((r & 7) << 2);
            float4 v;
            const float* p = A + (long)(m0 + r) * lda + k;
            if (k + 4 <= K) v = *(const float4*)p;
            else { v.x = k < K ? p[0] : 0.f; v.y = k + 1 < K ? p[1] : 0.f;
                   v.z = k + 2 < K ? p[2] : 0.f; v.w = k + 3 < K ? p[3] : 0.f; }
            *(float4*)&As[r * 32 + sc] = v;
            const float* q = B + (long)(n0 + r) * ldb + k;
            if (k + 4 <= K) v = *(const float4*)q;
            else { v.x = k < K ? q[0] : 0.f; v.y = k + 1 < K ? q[1] : 0.f;
                   v.z = k + 2 < K ? q[2] : 0.f; v.w = k + 3 < K ? q[3] : 0.f; }
            *(float4*)&Bs[r * 32 + sc] = v;
        }
        __syncthreads();
#pragma unroll
        for (int ks = 0; ks < 4; ks++) {
            int k0 = ks * 8;
            unsigned af[2][4], bf[8][2];
#pragma unroll
            for (int mt = 0; mt < 2; mt++) {
                int r = wm * 32 + mt * 16 + (lane >> 2);
                int c = k0 + (lane & 3);
                int sw = (r & 7) << 2;
                int r8 = r + 8, sw8 = (r8 & 7) << 2;
                af[mt][0] = tf32r(As[r  * 32 + (c ^ sw)]);
                af[mt][1] = tf32r(As[r8 * 32 + (c ^ sw8)]);
                af[mt][2] = tf32r(As[r  * 32 + ((c + 4) ^ sw)]);
                af[mt][3] = tf32r(As[r8 * 32 + ((c + 4) ^ sw8)]);
            }
#pragma unroll
            for (int nt = 0; nt < 8; nt++) {
                int rn = wn * 64 + nt * 8 + (lane >> 2);
                int ck = k0 + (lane & 3);
                int sw = (rn & 7) << 2;
                bf[nt][0] = tf32r(Bs[rn * 32 + (ck ^ sw)]);
                bf[nt][1] = tf32r(Bs[rn * 32 + ((ck + 4) ^ sw)]);
            }
#pragma unroll
            for (int mt = 0; mt < 2; mt++)
#pragma unroll
                for (int nt = 0; nt < 8; nt++) {
                    asm volatile(
                        "mma.sync.aligned.m16n8k8.row.col.f32.tf32.tf32.f32 "
                        "{%0,%1,%2,%3}, {%4,%5,%6,%7}, {%8,%9}, {%0,%1,%2,%3};\n"
                        : "+f"(acc[mt][nt][0]), "+f"(acc[mt][nt][1]),
                          "+f"(acc[mt][nt][2]), "+f"(acc[mt][nt][3])
                        : "r"(af[mt][0]), "r"(af[mt][1]), "r"(af[mt][2]), "r"(af[mt][3]),
                          "r"(bf[nt][0]), "r"(bf[nt][1]));
                }
        }
        __syncthreads();
    }
#pragma unroll
    for (int mt = 0; mt < 2; mt++) {
        int r = m0 + wm * 32 + mt * 16 + (lane >> 2);
#pragma unroll
        for (int nt = 0; nt < 8; nt++) {
            int c = n0 + wn * 64 + nt * 8 + (lane & 3) * 2;
            const float* bp = bias + (long)z * biasStr;
            float b0 = bp[c], b1 = bp[c + 1];
            float v0 = acc[mt][nt][0] + b0, v1 = acc[mt][nt][1] + b1;
            float v2 = acc[mt][nt][2] + b0, v3 = acc[mt][nt][3] + b1;
            if (EPI == 2) {
                v0 = fmaxf(v0, 0.f); v1 = fmaxf(v1, 0.f);
                v2 = fmaxf(v2, 0.f); v3 = fmaxf(v3, 0.f);
            }
            *(float2*)&C[(long)r * ldc + c]       = make_float2(v0, v1);
            *(float2*)&C[(long)(r + 8) * ldc + c] = make_float2(v2, v3);
        }
    }
}

// ---------------- rec-expert fc GEMM, compact A, scatter epilogue ----------------
__global__ __launch_bounds__(256, 2) void fc_gemm_scatter(
    const float* __restrict__ A,           // compact hLast, stride BB*HH per expert
    const float* __restrict__ B,           // fcW
    float* __restrict__ C,                 // g_eo (dense, batch-indexed)
    const float* __restrict__ bias)        // fcb
{
    __shared__ float As[128 * 32], Bs[128 * 32];
    int z = blockIdx.z;
    int cnt = g_cnt[z];
    if ((int)blockIdx.y * 128 >= cnt) return;
    A += (long)z * BB * HH;
    B += (long)z * OUTD * HH;
    C += (long)z * BB * OUTD;
    int m0 = blockIdx.y * 128, n0 = blockIdx.x * 128;
    int tid = threadIdx.x, lane = tid & 31, wid = tid >> 5;
    int wm = wid >> 1, wn = wid & 1;
    float acc[2][8][4] = {};

    for (int kb = 0; kb < HH; kb += 32) {
#pragma unroll
        for (int i = 0; i < 4; i++) {
            int f = tid + i * 256;
            int r = f >> 3, c4 = (f & 7) * 4;
            int sc = c4 ^ ((r & 7) << 2);
            *(float4*)&As[r * 32 + sc] = *(const float4*)(A + (long)(m0 + r) * HH + kb + c4);
            *(float4*)&Bs[r * 32 + sc] = *(const float4*)(B + (long)(n0 + r) * HH + kb + c4);
        }
        __syncthreads();
#pragma unroll
        for (int ks = 0; ks < 4; ks++) {
            int k0 = ks * 8;
            unsigned af[2][4], bf[8][2];
#pragma unroll
            for (int mt = 0; mt < 2; mt++) {
                int r = wm * 32 + mt * 16 + (lane >> 2);
                int c = k0 + (lane & 3);
                int sw = (r & 7) << 2;
                int r8 = r + 8, sw8 = (r8 & 7) << 2;
                af[mt][0] = tf32r(As[r  * 32 + (c ^ sw)]);
                af[mt][1] = tf32r(As[r8 * 32 + (c ^ sw8)]);
                af[mt][2] = tf32r(As[r  * 32 + ((c + 4) ^ sw)]);
                af[mt][3] = tf32r(As[r8 * 32 + ((c + 4) ^ sw8)]);
            }
#pragma unroll
            for (int nt = 0; nt < 8; nt++) {
                int rn = wn * 64 + nt * 8 + (lane >> 2);
                int ck = k0 + (lane & 3);
                int sw = (rn & 7) << 2;
                bf[nt][0] = tf32r(Bs[rn * 32 + (ck ^ sw)]);
                bf[nt][1] = tf32r(Bs[rn * 32 + ((ck + 4) ^ sw)]);
            }
#pragma unroll
            for (int mt = 0; mt < 2; mt++)
#pragma unroll
                for (int nt = 0; nt < 8; nt++) {
                    asm volatile(
                        "mma.sync.aligned.m16n8k8.row.col.f32.tf32.tf32.f32 "
                        "{%0,%1,%2,%3}, {%4,%5,%6,%7}, {%8,%9}, {%0,%1,%2,%3};\n"
                        : "+f"(acc[mt][nt][0]), "+f"(acc[mt][nt][1]),
                          "+f"(acc[mt][nt][2]), "+f"(acc[mt][nt][3])
                        : "r"(af[mt][0]), "r"(af[mt][1]), "r"(af[mt][2]), "r"(af[mt][3]),
                          "r"(bf[nt][0]), "r"(bf[nt][1]));
                }
        }
        __syncthreads();
    }
#pragma unroll
    for (int mt = 0; mt < 2; mt++) {
        int r = m0 + wm * 32 + mt * 16 + (lane >> 2);
        int bi0 = (r < cnt)     ? g_idx[z * BB + r]     : -1;
        int bi1 = (r + 8 < cnt) ? g_idx[z * BB + r + 8] : -1;
#pragma unroll
        for (int nt = 0; nt < 8; nt++) {
            int c = n0 + wn * 64 + nt * 8 + (lane & 3) * 2;
            const float* bp = bias + (long)z * OUTD;
            float b0 = bp[c], b1 = bp[c + 1];
            if (bi0 >= 0)
                *(float2*)&C[(long)bi0 * OUTD + c] =
                    make_float2(acc[mt][nt][0] + b0, acc[mt][nt][1] + b1);
            if (bi1 >= 0)
                *(float2*)&C[(long)bi1 * OUTD + c] =
                    make_float2(acc[mt][nt][2] + b0, acc[mt][nt][3] + b1);
        }
    }
}

// ---------------- final combine ----------------
__global__ void combine_kernel(float* __restrict__ out) {
    int idx = blockIdx.x * blockDim.x + threadIdx.x;  // B*OUT
    int b = idx >> 9, o = idx & 511;
    float s = 0.f;
#pragma unroll
    for (int e = 0; e < NE; e++)
        s += g_w[b * NE + e] * g_eo[((long)e * BB + b) * OUTD + o];
    out[idx] = s;
}

// ---------------- launch ----------------
extern "C" void kernel_launch(void* const* d_in, const int* in_sizes, int n_in,
                              void* d_out, int out_size)
{
    const float* x    = (const float*)d_in[0];
    const float* Wg   = (const float*)d_in[1];
    const float* bg   = (const float*)d_in[2];
    const float* Wih  = (const float*)d_in[3];
    const float* Whh  = (const float*)d_in[4];
    const float* bih  = (const float*)d_in[5];
    const float* bhh  = (const float*)d_in[6];
    const float* fcW  = (const float*)d_in[7];
    const float* fcb  = (const float*)d_in[8];
    const float* W1   = (const float*)d_in[9];
    const float* b1   = (const float*)d_in[10];
    const float* W2   = (const float*)d_in[11];
    const float* b2   = (const float*)d_in[12];
    float* out = (float*)d_out;

    const int LG_SMEM = 512 + 98304;   // idx stage + 3x(16K+16K)
    cudaFuncSetAttribute(lstm_gemm, cudaFuncAttributeMaxDynamicSharedMemorySize, LG_SMEM);

    float *xp, *h0p, *wp, *eop, *h1buf;
    cudaGetSymbolAddress((void**)&xp,    g_xpad);
    cudaGetSymbolAddress((void**)&h0p,   g_h);
    cudaGetSymbolAddress((void**)&wp,    g_w);
    cudaGetSymbolAddress((void**)&eop,   g_eo);
    cudaGetSymbolAddress((void**)&h1buf, g_h1);
    float* h1p = h0p + (size_t)NER * BB * HH;
    float* hbuf[2] = { h0p, h1p };

    // 5 launches before the first lstm_gemm (ncu -s 5 profiles lstm_gemm)
    prep_wcat<<<(int)(((long)NER * G4H * KCAT + 255) / 256), 256>>>(Whh, Wih);
    prep_bcat<<<(NER * G4H) / 256, 256>>>(bih, bhh);
    prep_xpad<<<(TT * BB * 32) / 256, 256>>>(x);
    gate_kernel<<<BB, 256>>>(x, Wg, bg, wp);
    compact_kernel<<<NER, 1024>>>();

    // recurrent steps (compact rows)
    for (int t = 0; t < TT; t++) {
        lstm_gemm<<<dim3(16, 16, NER), 256, LG_SMEM>>>(
            hbuf[t & 1], hbuf[(t + 1) & 1], xp + (size_t)t * BB * 32, t == 0 ? 512 : 0);
    }
    float* hLast = hbuf[TT & 1];

    // rec_out (compact -> scatter into dense g_eo[0..3])
    fc_gemm_scatter<<<dim3(4, 16, NER), 256>>>(hLast, fcW, eop, fcb);

    // h1 = relu(x @ W1^T + b1)
    gemm_tf32<2><<<dim3(4, 16, NER), 256>>>(
        x, IND, 0,
        W1, IND, (long)HH * IND,
        h1buf, HH, (long)BB * HH,
        b1, HH, IND);

    // simp = h1 @ W2^T + b2 -> g_eo[4..7]
    gemm_tf32<1><<<dim3(4, 16, NER), 256>>>(
        h1buf, HH, (long)BB * HH,
        W2, HH, (long)OUTD * HH,
        eop + (size_t)NER * BB * OUTD, OUTD, (long)BB * OUTD,
        b2, OUTD, HH);

    combine_kernel<<<(BB * OUTD) / 256, 256>>>(out);
}

// round 8
// speedup vs baseline: 3.5545x; 1.6335x over previous
#include <cuda_runtime.h>
#include <math.h>

#define BB   2048
#define IND  784
#define HH   512
#define OUTD 512
#define NE   8
#define NER  4
#define TT   28
#define G4H  2048
#define KCAT 544

// ---------------- device scratch (no allocation) ----------------
__device__ float g_Wcat[(size_t)NER * G4H * KCAT];   // interleaved [i,f,g,o]/unit, tf32-rounded
__device__ float g_bcat[NER * G4H];                  // bih+bhh, interleaved
__device__ float g_xpad[TT * BB * 32];               // x slices, tf32-rounded, padded
__device__ float g_h[2][(size_t)NER * BB * HH];      // ping-pong hidden, COMPACT rows
__device__ float g_c[(size_t)NER * BB * HH];         // cell state fp32, COMPACT rows
__device__ float g_w[BB * NE];
__device__ float g_eo[(size_t)NE * BB * OUTD];       // zero-init; only selected rows written (e<4)
__device__ float g_h1[(size_t)NER * BB * HH];
__device__ int   g_sel[NE * BB];                     // selection mask, expert-major
__device__ int   g_idx[NER * BB];                    // compact->batch index per expert
__device__ int   g_cnt[NER];                         // selected count per expert

// ---------------- helpers ----------------
__device__ __forceinline__ unsigned tf32r(float x) {
    unsigned u; asm("cvt.rna.tf32.f32 %0, %1;" : "=r"(u) : "f"(x)); return u;
}
__device__ __forceinline__ float tf32f(float x) { return __uint_as_float(tf32r(x)); }
__device__ __forceinline__ float fsig(float x) {
    float e; asm("ex2.approx.f32 %0, %1;" : "=f"(e) : "f"(-1.4426950408889634f * x));
    float r; asm("rcp.approx.f32 %0, %1;" : "=f"(r) : "f"(1.0f + e));
    return r;
}
__device__ __forceinline__ float ftanh_(float x) { return fmaf(2.0f, fsig(2.0f * x), -1.0f); }
__device__ __forceinline__ void cpa16(float* dst, const float* src) {
    unsigned d = (unsigned)__cvta_generic_to_shared(dst);
    asm volatile("cp.async.cg.shared.global [%0], [%1], 16;\n" :: "r"(d), "l"(src));
}
__device__ __forceinline__ void commitg() { asm volatile("cp.async.commit_group;\n"); }
__device__ __forceinline__ void ldsm4(unsigned& r0, unsigned& r1, unsigned& r2, unsigned& r3,
                                      unsigned addr) {
    asm volatile("ldmatrix.sync.aligned.m8n8.x4.shared.b16 {%0,%1,%2,%3}, [%4];"
                 : "=r"(r0), "=r"(r1), "=r"(r2), "=r"(r3) : "r"(addr));
}

// ---------------- gate: softmax / top-5 / renorm (fp32 exact) + selection mask ----------------
__global__ void gate_kernel(const float* __restrict__ x, const float* __restrict__ Wg,
                            const float* __restrict__ bg, float* __restrict__ w)
{
    int b = blockIdx.x;
    int lane = threadIdx.x & 31, wid = threadIdx.x >> 5;
    __shared__ float sc[NE];
    const float* xr = x + (long)b * IND;
    const float* wr = Wg + (long)wid * IND;
    float s = 0.f;
    for (int i = lane; i < IND; i += 32) s += xr[i] * wr[i];
#pragma unroll
    for (int o = 16; o; o >>= 1) s += __shfl_xor_sync(0xffffffffu, s, o);
    if (lane == 0) sc[wid] = s + bg[wid];
    __syncthreads();
    if (threadIdx.x == 0) {
        float p[NE], mx = -1e30f;
#pragma unroll
        for (int e = 0; e < NE; e++) { p[e] = sc[e] * (1.0f / 2.718281828459045f); mx = fmaxf(mx, p[e]); }
        float sum = 0.f;
#pragma unroll
        for (int e = 0; e < NE; e++) { p[e] = expf(p[e] - mx); sum += p[e]; }
#pragma unroll
        for (int e = 0; e < NE; e++) p[e] /= sum;
        float ws = 0.f, wv[NE];
        int selv[NE];
#pragma unroll
        for (int e = 0; e < NE; e++) {
            int rank = 0;
#pragma unroll
            for (int j = 0; j < NE; j++)
                if (p[j] > p[e] || (p[j] == p[e] && j < e)) rank++;
            selv[e] = (rank < 5) ? 1 : 0;
            wv[e] = selv[e] ? p[e] : 0.f;
            ws += wv[e];
        }
        float inv = 1.0f / (ws + 1e-8f);
#pragma unroll
        for (int e = 0; e < NE; e++) {
            w[b * NE + e] = wv[e] * inv;
            g_sel[e * BB + b] = selv[e];
        }
    }
}

// ---------------- per-expert compaction (block scan, 1024 thr, 2048 elems) ----------------
__global__ void compact_kernel() {
    int e = blockIdx.x;             // NER
    int tid = threadIdx.x;          // 1024
    __shared__ int scn[BB];
    scn[tid]        = g_sel[e * BB + tid];
    scn[tid + 1024] = g_sel[e * BB + tid + 1024];
    __syncthreads();
    for (int off = 1; off < BB; off <<= 1) {
        int v0 = (tid >= off) ? scn[tid - off] : 0;
        int v1 = (tid + 1024 >= off) ? scn[tid + 1024 - off] : 0;
        __syncthreads();
        scn[tid] += v0; scn[tid + 1024] += v1;
        __syncthreads();
    }
    int cnt = scn[BB - 1];
    if (g_sel[e * BB + tid])        g_idx[e * BB + scn[tid] - 1] = tid;
    if (g_sel[e * BB + tid + 1024]) g_idx[e * BB + scn[tid + 1024] - 1] = tid + 1024;
    if (tid + cnt < BB)        g_idx[e * BB + cnt + tid] = 0;
    if (tid + 1024 + cnt < BB) g_idx[e * BB + cnt + tid + 1024] = 0;
    if (tid == 0) g_cnt[e] = cnt;
}

// ---------------- fused prep: Wcat + bcat + xpad + c-init ----------------
__global__ void prep_all(const float* __restrict__ Whh, const float* __restrict__ Wih,
                         const float* __restrict__ bih, const float* __restrict__ bhh,
                         const float* __restrict__ x)
{
    long i = (long)blockIdx.x * 256 + threadIdx.x;
    if (i < (long)NER * G4H * KCAT) {
        int col = (int)(i % KCAT);
        long rr = i / KCAT;
        int row = (int)(rr % G4H);
        int e = (int)(rr / G4H);
        int u = row >> 2, g = row & 3;
        int orow = g * 512 + u;
        float v = 0.0f;
        if (col < 512)      v = Whh[((long)e * G4H + orow) * HH + col];
        else if (col < 540) v = Wih[((long)e * G4H + orow) * 28 + (col - 512)];
        g_Wcat[i] = tf32f(v);
    }
    if (i < NER * G4H) {
        int row = (int)(i & (G4H - 1)), e = (int)(i >> 11);
        int u = row >> 2, g = row & 3;
        int orow = g * 512 + u;
        g_bcat[i] = bih[e * G4H + orow] + bhh[e * G4H + orow];
    }
    if (i < (long)TT * BB * 32) {
        int j = (int)(i & 31), b = (int)((i >> 5) & (BB - 1)), t = (int)(i >> 16);
        g_xpad[i] = (j < 28) ? tf32f(x[(long)b * IND + t * 28 + j]) : 0.0f;
    }
    if (i < (long)NER * BB * HH) g_c[i] = 0.0f;
}

// ---------------- fused recurrent GEMM + LSTM cell (COMPACT rows) ----------------
// 3-stage cp.async pipeline, ldmatrix fragment loads, coalesced smem-staged epilogue.
__global__ __launch_bounds__(256, 2) void lstm_gemm(
    const float* __restrict__ hIn, float* __restrict__ hOut,
    const float* __restrict__ xpadT, int kStart)
{
    extern __shared__ float sm[];
    int* sIdx = (int*)sm;                       // 128 ints
    float* stg = sm + 128;                      // stages base (24576 floats)
    unsigned sBase = (unsigned)__cvta_generic_to_shared(stg);
    int e = blockIdx.z;
    int cnt = g_cnt[e];
    int tiles = (cnt + 127) >> 7;
    if ((int)blockIdx.y >= tiles) return;
    const float* Ah = hIn + (size_t)e * BB * HH;
    const float* Bw = g_Wcat + (size_t)e * G4H * KCAT;
    int m0 = blockIdx.y * 128, n0 = blockIdx.x * 128;
    int tid = threadIdx.x, lane = tid & 31, wid = tid >> 5;
    int wm = wid >> 1, wn = wid & 1;

    if (tid < 128) sIdx[tid] = g_idx[e * BB + m0 + tid];
    __syncthreads();

    float acc[2][8][4] = {};
    int NSl = (KCAT - kStart) >> 5;

    int lm_mat = lane >> 3, lm_row = lane & 7;
    unsigned swz = (unsigned)(lm_row << 2);
    unsigned aRow = (unsigned)(wm * 32 + (lm_mat & 1) * 8 + lm_row);
    unsigned aCol0 = (unsigned)((lm_mat >> 1) * 4);
    unsigned bRow = (unsigned)(wn * 64 + ((lm_mat >> 1) & 1) * 8 + lm_row);
    unsigned bCol0 = (unsigned)((lm_mat & 1) * 4);

#define LOAD_SLAB(stg_, slab) do {                                              \
        int kb = kStart + (slab) * 32;                                          \
        float* Ad = stg + (stg_) * 4096;                                        \
        float* Bd = stg + 12288 + (stg_) * 4096;                                \
        _Pragma("unroll")                                                       \
        for (int i_ = 0; i_ < 4; i_++) {                                        \
            int f_ = tid + i_ * 256;                                            \
            int r_ = f_ >> 3, c4_ = (f_ & 7) * 4;                               \
            int sc_ = c4_ ^ ((r_ & 7) << 2);                                    \
            const float* ga = (kb < 512)                                        \
                ? (Ah + (size_t)(m0 + r_) * HH + kb + c4_)                      \
                : (xpadT + (size_t)sIdx[r_] * 32 + c4_);                        \
            cpa16(Ad + r_ * 32 + sc_, ga);                                      \
            cpa16(Bd + r_ * 32 + sc_, Bw + (size_t)(n0 + r_) * KCAT + kb + c4_);\
        }                                                                       \
        commitg();                                                              \
    } while (0)

    LOAD_SLAB(0, 0);
    if (NSl > 1) LOAD_SLAB(1, 1);

    int stage = 0;
    for (int s = 0; s < NSl; s++) {
        if (s < NSl - 1) asm volatile("cp.async.wait_group 1;\n");
        else             asm volatile("cp.async.wait_group 0;\n");
        __syncthreads();
        if (s + 2 < NSl) {
            int nst = stage + 2; if (nst >= 3) nst -= 3;
            LOAD_SLAB(nst, s + 2);
        }
        unsigned aStage = sBase + (unsigned)(stage * 4096) * 4u;
        unsigned bStage = sBase + (unsigned)(12288 + stage * 4096) * 4u;
#pragma unroll
        for (int ks = 0; ks < 4; ks++) {
            unsigned kbase = (unsigned)(ks * 8);
            unsigned af[2][4], bf[8][2];
#pragma unroll
            for (int mt = 0; mt < 2; mt++) {
                unsigned r = aRow + (unsigned)(mt * 16);
                unsigned c = (kbase + aCol0) ^ swz;
                ldsm4(af[mt][0], af[mt][1], af[mt][2], af[mt][3],
                      aStage + (r * 32 + c) * 4u);
            }
#pragma unroll
            for (int pp = 0; pp < 4; pp++) {
                unsigned r = bRow + (unsigned)(pp * 16);
                unsigned c = (kbase + bCol0) ^ swz;
                ldsm4(bf[2 * pp][0], bf[2 * pp][1], bf[2 * pp + 1][0], bf[2 * pp + 1][1],
                      bStage + (r * 32 + c) * 4u);
            }
#pragma unroll
            for (int mt = 0; mt < 2; mt++)
#pragma unroll
                for (int nt = 0; nt < 8; nt++) {
                    asm volatile(
                        "mma.sync.aligned.m16n8k8.row.col.f32.tf32.tf32.f32 "
                        "{%0,%1,%2,%3}, {%4,%5,%6,%7}, {%8,%9}, {%0,%1,%2,%3};\n"
                        : "+f"(acc[mt][nt][0]), "+f"(acc[mt][nt][1]),
                          "+f"(acc[mt][nt][2]), "+f"(acc[mt][nt][3])
                        : "r"(af[mt][0]), "r"(af[mt][1]), "r"(af[mt][2]), "r"(af[mt][3]),
                          "r"(bf[nt][0]), "r"(bf[nt][1]));
                }
        }
        stage++; if (stage >= 3) stage = 0;
    }

    // -------- epilogue: stage gates in smem, then fully coalesced cell update --------
    __syncthreads();                                   // stages free for reuse
    float* sG = stg;                                   // [128][132] floats = 67.6KB
#pragma unroll
    for (int mt = 0; mt < 2; mt++) {
        int rl = wm * 32 + mt * 16 + (lane >> 2);
        int cl = wn * 64 + (lane & 3) * 2;
#pragma unroll
        for (int nt = 0; nt < 8; nt++) {
            *(float2*)&sG[rl * 132 + cl + nt * 8]       = make_float2(acc[mt][nt][0], acc[mt][nt][1]);
            *(float2*)&sG[(rl + 8) * 132 + cl + nt * 8] = make_float2(acc[mt][nt][2], acc[mt][nt][3]);
        }
    }
    __syncthreads();

    int g8 = tid & 7, r0 = tid >> 3;
    int ub = n0 >> 2;                                   // unit base for this CTA
    float* cP = g_c + (size_t)e * BB * HH;
    float* hP = hOut + (size_t)e * BB * HH;
    const float* bc = g_bcat + e * G4H + n0 + g8 * 16;
#pragma unroll
    for (int k = 0; k < 4; k++) {
        int rl = r0 + k * 32;
        int rg = m0 + rl;
        const float* gr = sG + rl * 132 + g8 * 16;
        size_t gofs = (size_t)rg * HH + ub + g8 * 4;
        float4 cold = *(const float4*)(cP + gofs);
        float co[4] = { cold.x, cold.y, cold.z, cold.w };
        float4 hnew, cnew;
        float* hn = (float*)&hnew;
        float* cn = (float*)&cnew;
#pragma unroll
        for (int j = 0; j < 4; j++) {
            float4 bb = *(const float4*)(bc + 4 * j);
            float gi = gr[4 * j + 0] + bb.x;
            float gf = gr[4 * j + 1] + bb.y;
            float gg = gr[4 * j + 2] + bb.z;
            float go = gr[4 * j + 3] + bb.w;
            float cv = fsig(gf) * co[j] + fsig(gi) * ftanh_(gg);
            cn[j] = cv;
            hn[j] = tf32f(fsig(go) * ftanh_(cv));
        }
        *(float4*)(cP + gofs) = cnew;
        *(float4*)(hP + gofs) = hnew;
    }
}

// ---------------- generic tf32 GEMM: C = A @ B^T (+bias)(+relu) ----------------
template<int EPI>  // 1 +bias, 2 +bias+relu
__global__ __launch_bounds__(256, 2) void gemm_tf32(
    const float* __restrict__ A, int lda, long aStr,
    const float* __restrict__ B, int ldb, long bStr,
    float* __restrict__ C, int ldc, long cStr,
    const float* __restrict__ bias, long biasStr, int K)
{
    __shared__ float As[128 * 32], Bs[128 * 32];
    int z = blockIdx.z;
    A += (long)z * aStr; B += (long)z * bStr; C += (long)z * cStr;
    int m0 = blockIdx.y * 128, n0 = blockIdx.x * 128;
    int tid = threadIdx.x, lane = tid & 31, wid = tid >> 5;
    int wm = wid >> 1, wn = wid & 1;
    float acc[2][8][4] = {};

    for (int kb = 0; kb < K; kb += 32) {
#pragma unroll
        for (int i = 0; i < 4; i++) {
            int f = tid + i * 256;
            int r = f >> 3, c4 = (f & 7) * 4;
            int k = kb + c4;
            int sc = c4 ^ ((r & 7) << 2);
            float4 v;
            const float* p = A + (long)(m0 + r) * lda + k;
            if (k + 4 <= K) v = *(const float4*)p;
            else { v.x = k < K ? p[0] : 0.f; v.y = k + 1 < K ? p[1] : 0.f;
                   v.z = k + 2 < K ? p[2] : 0.f; v.w = k + 3 < K ? p[3] : 0.f; }
            *(float4*)&As[r * 32 + sc] = v;
            const float* q = B + (long)(n0 + r) * ldb + k;
            if (k + 4 <= K) v = *(const float4*)q;
            else { v.x = k < K ? q[0] : 0.f; v.y = k + 1 < K ? q[1] : 0.f;
                   v.z = k + 2 < K ? q[2] : 0.f; v.w = k + 3 < K ? q[3] : 0.f; }
            *(float4*)&Bs[r * 32 + sc] = v;
        }
        __syncthreads();
#pragma unroll
        for (int ks = 0; ks < 4; ks++) {
            int k0 = ks * 8;
            unsigned af[2][4], bf[8][2];
#pragma unroll
            for (int mt = 0; mt < 2; mt++) {
                int r = wm * 32 + mt * 16 + (lane >> 2);
                int c = k0 + (lane & 3);
                int sw = (r & 7) << 2;
                int r8 = r + 8, sw8 = (r8 & 7) << 2;
                af[mt][0] = tf32r(As[r  * 32 + (c ^ sw)]);
                af[mt][1] = tf32r(As[r8 * 32 + (c ^ sw8)]);
                af[mt][2] = tf32r(As[r  * 32 + ((c + 4) ^ sw)]);
                af[mt][3] = tf32r(As[r8 * 32 + ((c + 4) ^ sw8)]);
            }
#pragma unroll
            for (int nt = 0; nt < 8; nt++) {
                int rn = wn * 64 + nt * 8 + (lane >> 2);
                int ck = k0 + (lane & 3);
                int sw = (rn & 7) << 2;
                bf[nt][0] = tf32r(Bs[rn * 32 + (ck ^ sw)]);
                bf[nt][1] = tf32r(Bs[rn * 32 + ((ck + 4) ^ sw)]);
            }
#pragma unroll
            for (int mt = 0; mt < 2; mt++)
#pragma unroll
                for (int nt = 0; nt < 8; nt++) {
                    asm volatile(
                        "mma.sync.aligned.m16n8k8.row.col.f32.tf32.tf32.f32 "
                        "{%0,%1,%2,%3}, {%4,%5,%6,%7}, {%8,%9}, {%0,%1,%2,%3};\n"
                        : "+f"(acc[mt][nt][0]), "+f"(acc[mt][nt][1]),
                          "+f"(acc[mt][nt][2]), "+f"(acc[mt][nt][3])
                        : "r"(af[mt][0]), "r"(af[mt][1]), "r"(af[mt][2]), "r"(af[mt][3]),
                          "r"(bf[nt][0]), "r"(bf[nt][1]));
                }
        }
        __syncthreads();
    }
#pragma unroll
    for (int mt = 0; mt < 2; mt++) {
        int r = m0 + wm * 32 + mt * 16 + (lane >> 2);
#pragma unroll
        for (int nt = 0; nt < 8; nt++) {
            int c = n0 + wn * 64 + nt * 8 + (lane & 3) * 2;
            const float* bp = bias + (long)z * biasStr;
            float b0 = bp[c], b1 = bp[c + 1];
            float v0 = acc[mt][nt][0] + b0, v1 = acc[mt][nt][1] + b1;
            float v2 = acc[mt][nt][2] + b0, v3 = acc[mt][nt][3] + b1;
            if (EPI == 2) {
                v0 = fmaxf(v0, 0.f); v1 = fmaxf(v1, 0.f);
                v2 = fmaxf(v2, 0.f); v3 = fmaxf(v3, 0.f);
            }
            *(float2*)&C[(long)r * ldc + c]       = make_float2(v0, v1);
            *(float2*)&C[(long)(r + 8) * ldc + c] = make_float2(v2, v3);
        }
    }
}

// ---------------- rec-expert fc GEMM, compact A, scatter epilogue ----------------
__global__ __launch_bounds__(256, 2) void fc_gemm_scatter(
    const float* __restrict__ A, const float* __restrict__ B,
    float* __restrict__ C, const float* __restrict__ bias)
{
    __shared__ float As[128 * 32], Bs[128 * 32];
    int z = blockIdx.z;
    int cnt = g_cnt[z];
    if ((int)blockIdx.y * 128 >= cnt) return;
    A += (long)z * BB * HH;
    B += (long)z * OUTD * HH;
    C += (long)z * BB * OUTD;
    int m0 = blockIdx.y * 128, n0 = blockIdx.x * 128;
    int tid = threadIdx.x, lane = tid & 31, wid = tid >> 5;
    int wm = wid >> 1, wn = wid & 1;
    float acc[2][8][4] = {};

    for (int kb = 0; kb < HH; kb += 32) {
#pragma unroll
        for (int i = 0; i < 4; i++) {
            int f = tid + i * 256;
            int r = f >> 3, c4 = (f & 7) * 4;
            int sc = c4 ^ ((r & 7) << 2);
            *(float4*)&As[r * 32 + sc] = *(const float4*)(A + (long)(m0 + r) * HH + kb + c4);
            *(float4*)&Bs[r * 32 + sc] = *(const float4*)(B + (long)(n0 + r) * HH + kb + c4);
        }
        __syncthreads();
#pragma unroll
        for (int ks = 0; ks < 4; ks++) {
            int k0 = ks * 8;
            unsigned af[2][4], bf[8][2];
#pragma unroll
            for (int mt = 0; mt < 2; mt++) {
                int r = wm * 32 + mt * 16 + (lane >> 2);
                int c = k0 + (lane & 3);
                int sw = (r & 7) << 2;
                int r8 = r + 8, sw8 = (r8 & 7) << 2;
                af[mt][0] = tf32r(As[r  * 32 + (c ^ sw)]);
                af[mt][1] = tf32r(As[r8 * 32 + (c ^ sw8)]);
                af[mt][2] = tf32r(As[r  * 32 + ((c + 4) ^ sw)]);
                af[mt][3] = tf32r(As[r8 * 32 + ((c + 4) ^ sw8)]);
            }
#pragma unroll
            for (int nt = 0; nt < 8; nt++) {
                int rn = wn * 64 + nt * 8 + (lane >> 2);
                int ck = k0 + (lane & 3);
                int sw = (rn & 7) << 2;
                bf[nt][0] = tf32r(Bs[rn * 32 + (ck ^ sw)]);
                bf[nt][1] = tf32r(Bs[rn * 32 + ((ck + 4) ^ sw)]);
            }
#pragma unroll
            for (int mt = 0; mt < 2; mt++)
#pragma unroll
                for (int nt = 0; nt < 8; nt++) {
                    asm volatile(
                        "mma.sync.aligned.m16n8k8.row.col.f32.tf32.tf32.f32 "
                        "{%0,%1,%2,%3}, {%4,%5,%6,%7}, {%8,%9}, {%0,%1,%2,%3};\n"
                        : "+f"(acc[mt][nt][0]), "+f"(acc[mt][nt][1]),
                          "+f"(acc[mt][nt][2]), "+f"(acc[mt][nt][3])
                        : "r"(af[mt][0]), "r"(af[mt][1]), "r"(af[mt][2]), "r"(af[mt][3]),
                          "r"(bf[nt][0]), "r"(bf[nt][1]));
                }
        }
        __syncthreads();
    }
#pragma unroll
    for (int mt = 0; mt < 2; mt++) {
        int r = m0 + wm * 32 + mt * 16 + (lane >> 2);
        int bi0 = (r < cnt)     ? g_idx[z * BB + r]     : -1;
        int bi1 = (r + 8 < cnt) ? g_idx[z * BB + r + 8] : -1;
#pragma unroll
        for (int nt = 0; nt < 8; nt++) {
            int c = n0 + wn * 64 + nt * 8 + (lane & 3) * 2;
            const float* bp = bias + (long)z * OUTD;
            float b0 = bp[c], b1 = bp[c + 1];
            if (bi0 >= 0)
                *(float2*)&C[(long)bi0 * OUTD + c] =
                    make_float2(acc[mt][nt][0] + b0, acc[mt][nt][1] + b1);
            if (bi1 >= 0)
                *(float2*)&C[(long)bi1 * OUTD + c] =
                    make_float2(acc[mt][nt][2] + b0, acc[mt][nt][3] + b1);
        }
    }
}

// ---------------- final combine ----------------
__global__ void combine_kernel(float* __restrict__ out) {
    int idx = blockIdx.x * blockDim.x + threadIdx.x;  // B*OUT
    int b = idx >> 9, o = idx & 511;
    float s = 0.f;
#pragma unroll
    for (int e = 0; e < NE; e++)
        s += g_w[b * NE + e] * g_eo[((long)e * BB + b) * OUTD + o];
    out[idx] = s;
}

// ---------------- launch ----------------
extern "C" void kernel_launch(void* const* d_in, const int* in_sizes, int n_in,
                              void* d_out, int out_size)
{
    const float* x    = (const float*)d_in[0];
    const float* Wg   = (const float*)d_in[1];
    const float* bg   = (const float*)d_in[2];
    const float* Wih  = (const float*)d_in[3];
    const float* Whh  = (const float*)d_in[4];
    const float* bih  = (const float*)d_in[5];
    const float* bhh  = (const float*)d_in[6];
    const float* fcW  = (const float*)d_in[7];
    const float* fcb  = (const float*)d_in[8];
    const float* W1   = (const float*)d_in[9];
    const float* b1   = (const float*)d_in[10];
    const float* W2   = (const float*)d_in[11];
    const float* b2   = (const float*)d_in[12];
    float* out = (float*)d_out;

    const int LG_SMEM = 512 + 98304;
    cudaFuncSetAttribute(lstm_gemm, cudaFuncAttributeMaxDynamicSharedMemorySize, LG_SMEM);

    float *xp, *h0p, *wp, *eop, *h1buf;
    cudaGetSymbolAddress((void**)&xp,    g_xpad);
    cudaGetSymbolAddress((void**)&h0p,   g_h);
    cudaGetSymbolAddress((void**)&wp,    g_w);
    cudaGetSymbolAddress((void**)&eop,   g_eo);
    cudaGetSymbolAddress((void**)&h1buf, g_h1);
    float* h1p = h0p + (size_t)NER * BB * HH;
    float* hbuf[2] = { h0p, h1p };

    // 3 launches before lstm_gemm -> profiler (4th launch) lands on the hot kernel
    gate_kernel<<<BB, 256>>>(x, Wg, bg, wp);
    compact_kernel<<<NER, 1024>>>();
    prep_all<<<(int)(((long)NER * G4H * KCAT + 255) / 256), 256>>>(Whh, Wih, bih, bhh, x);

    for (int t = 0; t < TT; t++) {
        lstm_gemm<<<dim3(16, 16, NER), 256, LG_SMEM>>>(
            hbuf[t & 1], hbuf[(t + 1) & 1], xp + (size_t)t * BB * 32, t == 0 ? 512 : 0);
    }
    float* hLast = hbuf[TT & 1];

    fc_gemm_scatter<<<dim3(4, 16, NER), 256>>>(hLast, fcW, eop, fcb);

    gemm_tf32<2><<<dim3(4, 16, NER), 256>>>(
        x, IND, 0,
        W1, IND, (long)HH * IND,
        h1buf, HH, (long)BB * HH,
        b1, HH, IND);

    gemm_tf32<1><<<dim3(4, 16, NER), 256>>>(
        h1buf, HH, (long)BB * HH,
        W2, HH, (long)OUTD * HH,
        eop + (size_t)NER * BB * OUTD, OUTD, (long)BB * OUTD,
        b2, OUTD, HH);

    combine_kernel<<<(BB * OUTD) / 256, 256>>>(out);
}